// round 5
// baseline (speedup 1.0000x reference)
#include <cuda_runtime.h>
#include <math.h>

// Problem constants
#define TSEQ 2048
#define CEMB 1024
#define MTOT 8192   // B*T
#define DFF  4096

// ---------------- scratch (device globals; no allocation allowed) ------------
__device__ float g_h  [(size_t)MTOT * CEMB];  // layernorm output (reused ln1/ln2)
__device__ float g_q  [(size_t)MTOT * CEMB];
__device__ float g_k  [(size_t)MTOT * CEMB];
__device__ float g_v  [(size_t)MTOT * CEMB];
__device__ float g_att[(size_t)MTOT * CEMB];
__device__ float g_x1 [(size_t)MTOT * CEMB];  // x after attention sublayer
__device__ float g_ff [(size_t)MTOT * DFF];   // ffn hidden

// ---------------- LayerNorm: one block per row, 256 threads, C=1024 ----------
__global__ __launch_bounds__(256)
void ln_kernel(const float* __restrict__ x, const float* __restrict__ w,
               const float* __restrict__ bb, float* __restrict__ out)
{
    __shared__ float sred[8];
    __shared__ float s_mu, s_var;
    const int row = blockIdx.x;
    const int tid = threadIdx.x;

    float4 v = ((const float4*)(x + (size_t)row * CEMB))[tid];
    float s = v.x + v.y + v.z + v.w;
    #pragma unroll
    for (int o = 16; o > 0; o >>= 1) s += __shfl_down_sync(0xffffffffu, s, o);
    if ((tid & 31) == 0) sred[tid >> 5] = s;
    __syncthreads();
    if (tid == 0) {
        float t = 0.f;
        #pragma unroll
        for (int i = 0; i < 8; i++) t += sred[i];
        s_mu = t * (1.f / 1024.f);
    }
    __syncthreads();
    const float mu = s_mu;
    float a0 = v.x - mu, a1 = v.y - mu, a2 = v.z - mu, a3 = v.w - mu;
    float sq = a0 * a0 + a1 * a1 + a2 * a2 + a3 * a3;
    #pragma unroll
    for (int o = 16; o > 0; o >>= 1) sq += __shfl_down_sync(0xffffffffu, sq, o);
    if ((tid & 31) == 0) sred[tid >> 5] = sq;
    __syncthreads();
    if (tid == 0) {
        float t = 0.f;
        #pragma unroll
        for (int i = 0; i < 8; i++) t += sred[i];
        s_var = t * (1.f / 1024.f);
    }
    __syncthreads();
    const float r = rsqrtf(s_var + 1e-5f);
    float4 wv = ((const float4*)w)[tid];
    float4 bv = ((const float4*)bb)[tid];
    float4 o;
    o.x = a0 * r * wv.x + bv.x;
    o.y = a1 * r * wv.y + bv.y;
    o.z = a2 * r * wv.z + bv.z;
    o.w = a3 * r * wv.w + bv.w;
    ((float4*)(out + (size_t)row * CEMB))[tid] = o;
}

// ---------------- SGEMM: C[M,N] = A[M,K] @ B[K,N] (+ epilogue) ---------------
// MODE 0: plain store
// MODE 1: out = res + acc + bias
// MODE 2: out = relu(acc + bias)
// MODE 3: out = (res + acc + bias) * mask(row)
template<int MODE>
__global__ __launch_bounds__(256)
void sgemm_kernel(const float* __restrict__ Ag, const float* __restrict__ Bg,
                  float* __restrict__ Cg, const float* __restrict__ Rg,
                  const float* __restrict__ biasg,
                  const unsigned char* __restrict__ maskg,
                  int M, int N, int K)
{
    __shared__ float As[8][128];
    __shared__ float Bs[8][128];
    const int tid  = threadIdx.x;
    const int brow = blockIdx.y * 128;
    const int bcol = blockIdx.x * 128;
    const int arow = tid >> 1;
    const int acol = (tid & 1) * 4;
    const int brl  = tid >> 5;
    const int bcl  = (tid & 31) * 4;
    const int ty8  = (tid >> 4) * 8;
    const int tx8  = (tid & 15) * 8;

    unsigned int probe = 0;
    if (MODE == 3) probe = (unsigned int)maskg[1];  // t=1 always valid (len>=1024)

    float acc[8][8];
    #pragma unroll
    for (int i = 0; i < 8; i++)
        #pragma unroll
        for (int j = 0; j < 8; j++) acc[i][j] = 0.f;

    const float* Aload = Ag + (size_t)(brow + arow) * K + acol;
    const float* Bload = Bg + (size_t)brl * N + bcol + bcl;

    for (int k0 = 0; k0 < K; k0 += 8) {
        float4 av = *(const float4*)(Aload + k0);
        As[acol + 0][arow] = av.x;
        As[acol + 1][arow] = av.y;
        As[acol + 2][arow] = av.z;
        As[acol + 3][arow] = av.w;
        float4 bv2 = *(const float4*)(Bload + (size_t)k0 * N);
        *(float4*)&Bs[brl][bcl] = bv2;
        __syncthreads();
        #pragma unroll
        for (int kk = 0; kk < 8; kk++) {
            float ra[8], rb[8];
            *(float4*)&ra[0] = *(const float4*)&As[kk][ty8];
            *(float4*)&ra[4] = *(const float4*)&As[kk][ty8 + 4];
            *(float4*)&rb[0] = *(const float4*)&Bs[kk][tx8];
            *(float4*)&rb[4] = *(const float4*)&Bs[kk][tx8 + 4];
            #pragma unroll
            for (int i = 0; i < 8; i++)
                #pragma unroll
                for (int j = 0; j < 8; j++)
                    acc[i][j] = fmaf(ra[i], rb[j], acc[i][j]);
        }
        __syncthreads();
    }

    #pragma unroll
    for (int i = 0; i < 8; i++) {
        const size_t r    = (size_t)(brow + ty8 + i);
        const size_t base = r * N + bcol + tx8;
        float mrow = 1.f;
        if (MODE == 3) {
            mrow = probe ? (maskg[r] ? 1.f : 0.f)
                         : (((const unsigned int*)maskg)[r] ? 1.f : 0.f);
        }
        #pragma unroll
        for (int jj = 0; jj < 8; jj += 4) {
            float4 o;
            o.x = acc[i][jj + 0];
            o.y = acc[i][jj + 1];
            o.z = acc[i][jj + 2];
            o.w = acc[i][jj + 3];
            if (MODE == 1 || MODE == 3) {
                float4 rv = *(const float4*)(Rg + base + jj);
                o.x += rv.x; o.y += rv.y; o.z += rv.z; o.w += rv.w;
            }
            if (MODE >= 1) {
                float4 bb = *(const float4*)(biasg + bcol + tx8 + jj);
                o.x += bb.x; o.y += bb.y; o.z += bb.z; o.w += bb.w;
            }
            if (MODE == 2) {
                o.x = fmaxf(o.x, 0.f); o.y = fmaxf(o.y, 0.f);
                o.z = fmaxf(o.z, 0.f); o.w = fmaxf(o.w, 0.f);
            }
            if (MODE == 3) {
                o.x *= mrow; o.y *= mrow; o.z *= mrow; o.w *= mrow;
            }
            *(float4*)(Cg + base + jj) = o;
        }
    }
}

// ---------------- Flash attention (causal only), fp32 ------------------------
// grid (T/64, B*H); block 256 = 16x16 threads; each thread 4x4 of 64x64 tiles.
// smem rows padded to 65 floats to avoid bank conflicts on column access.
#define FPAD 65
#define FLASH_SMEM_FLOATS (3 * 64 * FPAD + 64 * 16 + 3 * 64)
#define FLASH_SMEM_BYTES  (FLASH_SMEM_FLOATS * 4)

__global__ __launch_bounds__(256)
void flash_kernel(const float* __restrict__ q, const float* __restrict__ k,
                  const float* __restrict__ v, float* __restrict__ o)
{
    extern __shared__ float sm[];
    float* Qs    = sm;                       // [64][FPAD]  Q[r][d]
    float* KP    = sm + 64 * FPAD;           // K[c][d], later P[s][r]
    float* Vs    = sm + 2 * 64 * FPAD;       // V[s][d]
    float* red   = sm + 3 * 64 * FPAD;       // [64][16]
    float* row_m = red + 64 * 16;
    float* row_l = row_m + 64;
    float* row_a = row_l + 64;

    const int qt  = blockIdx.x;
    const int bh  = blockIdx.y;
    const int bb  = bh >> 4;
    const int h   = bh & 15;
    const int tid = threadIdx.x;
    const int ty  = (tid >> 4) * 4;
    const int tx  = (tid & 15) * 4;
    const size_t rowbase = (size_t)bb * TSEQ;
    const int hoff = h * 64;
    const float NEG = __int_as_float(0xff800000);  // -inf

    // load Q tile [64 rows][64 dims], coalesced, row-major with pad
    for (int idx = tid; idx < 1024; idx += 256) {
        const int r  = idx >> 4;
        const int d4 = (idx & 15) * 4;
        float4 qv = *(const float4*)(q + (rowbase + (size_t)qt * 64 + r) * CEMB + hoff + d4);
        float* dst = Qs + r * FPAD + d4;
        dst[0] = qv.x; dst[1] = qv.y; dst[2] = qv.z; dst[3] = qv.w;
    }
    if (tid < 64) { row_m[tid] = NEG; row_l[tid] = 0.f; }

    float acc[4][4];
    #pragma unroll
    for (int i = 0; i < 4; i++)
        #pragma unroll
        for (int j = 0; j < 4; j++) acc[i][j] = 0.f;

    for (int jt = 0; jt <= qt; jt++) {
        // load K and V tiles
        for (int idx = tid; idx < 1024; idx += 256) {
            const int r  = idx >> 4;
            const int d4 = (idx & 15) * 4;
            const size_t gr = (rowbase + (size_t)jt * 64 + r) * CEMB + hoff + d4;
            float4 kv = *(const float4*)(k + gr);
            float* kd = KP + r * FPAD + d4;
            kd[0] = kv.x; kd[1] = kv.y; kd[2] = kv.z; kd[3] = kv.w;
            float4 vv = *(const float4*)(v + gr);
            float* vd = Vs + r * FPAD + d4;
            vd[0] = vv.x; vd[1] = vv.y; vd[2] = vv.z; vd[3] = vv.w;
        }
        __syncthreads();

        // S = Q K^T (4x4 per thread)
        float sc[4][4];
        #pragma unroll
        for (int i = 0; i < 4; i++)
            #pragma unroll
            for (int j = 0; j < 4; j++) sc[i][j] = 0.f;
        #pragma unroll 16
        for (int d = 0; d < 64; d++) {
            float ra[4], rb[4];
            #pragma unroll
            for (int i = 0; i < 4; i++) ra[i] = Qs[(ty + i) * FPAD + d];
            #pragma unroll
            for (int j = 0; j < 4; j++) rb[j] = KP[(tx + j) * FPAD + d];
            #pragma unroll
            for (int i = 0; i < 4; i++)
                #pragma unroll
                for (int j = 0; j < 4; j++)
                    sc[i][j] = fmaf(ra[i], rb[j], sc[i][j]);
        }
        const float scale = 0.03125f;  // 1024^-0.5
        #pragma unroll
        for (int i = 0; i < 4; i++)
            #pragma unroll
            for (int j = 0; j < 4; j++) {
                float val = sc[i][j] * scale;
                if (jt == qt && (tx + j) > (ty + i)) val = -1e30f;
                sc[i][j] = val;
            }

        // row max partial
        #pragma unroll
        for (int i = 0; i < 4; i++) {
            float mx = fmaxf(fmaxf(sc[i][0], sc[i][1]), fmaxf(sc[i][2], sc[i][3]));
            red[(ty + i) * 16 + (tid & 15)] = mx;
        }
        __syncthreads();
        if (tid < 64) {
            float mx = red[tid * 16];
            #pragma unroll
            for (int kk = 1; kk < 16; kk++) mx = fmaxf(mx, red[tid * 16 + kk]);
            const float mo = row_m[tid];
            const float mn = fmaxf(mo, mx);
            row_a[tid] = __expf(mo - mn);
            row_m[tid] = mn;
        }
        __syncthreads();

        // P = exp(S - m); write transposed P[s][r] (reuses K buffer)
        #pragma unroll
        for (int i = 0; i < 4; i++) {
            const float mrow = row_m[ty + i];
            float s0 = 0.f;
            #pragma unroll
            for (int j = 0; j < 4; j++) {
                const float p = __expf(sc[i][j] - mrow);
                KP[(tx + j) * FPAD + (ty + i)] = p;
                s0 += p;
            }
            red[(ty + i) * 16 + (tid & 15)] = s0;
        }
        __syncthreads();
        if (tid < 64) {
            float s0 = red[tid * 16];
            #pragma unroll
            for (int kk = 1; kk < 16; kk++) s0 += red[tid * 16 + kk];
            row_l[tid] = row_l[tid] * row_a[tid] + s0;
        }
        // rescale O by alpha
        #pragma unroll
        for (int i = 0; i < 4; i++) {
            const float a = row_a[ty + i];
            #pragma unroll
            for (int j = 0; j < 4; j++) acc[i][j] *= a;
        }
        // O += P @ V
        #pragma unroll 16
        for (int s = 0; s < 64; s++) {
            float rp[4], rv[4];
            #pragma unroll
            for (int i = 0; i < 4; i++) rp[i] = KP[s * FPAD + (ty + i)];
            #pragma unroll
            for (int j = 0; j < 4; j++) rv[j] = Vs[s * FPAD + (tx + j)];
            #pragma unroll
            for (int i = 0; i < 4; i++)
                #pragma unroll
                for (int j = 0; j < 4; j++)
                    acc[i][j] = fmaf(rp[i], rv[j], acc[i][j]);
        }
        __syncthreads();
    }

    #pragma unroll
    for (int i = 0; i < 4; i++) {
        const float inv = 1.f / row_l[ty + i];
        float4 ov;
        ov.x = acc[i][0] * inv;
        ov.y = acc[i][1] * inv;
        ov.z = acc[i][2] * inv;
        ov.w = acc[i][3] * inv;
        *(float4*)(o + (rowbase + (size_t)qt * 64 + ty + i) * CEMB + hoff + tx) = ov;
    }
}

// ---------------- launcher ---------------------------------------------------
extern "C" void kernel_launch(void* const* d_in, const int* in_sizes, int n_in,
                              void* d_out, int out_size)
{
    const float* x      = (const float*)d_in[0];
    const unsigned char* mask = (const unsigned char*)d_in[1];
    const float* wq     = (const float*)d_in[2];
    const float* wk     = (const float*)d_in[3];
    const float* wv     = (const float*)d_in[4];
    const float* proj_w = (const float*)d_in[5];
    const float* proj_b = (const float*)d_in[6];
    const float* ff_w1  = (const float*)d_in[7];
    const float* ff_b1  = (const float*)d_in[8];
    const float* ff_w2  = (const float*)d_in[9];
    const float* ff_b2  = (const float*)d_in[10];
    const float* ln1w   = (const float*)d_in[11];
    const float* ln1b   = (const float*)d_in[12];
    const float* ln2w   = (const float*)d_in[13];
    const float* ln2b   = (const float*)d_in[14];
    float* out = (float*)d_out;

    float *h, *q, *k, *v, *att, *x1, *ff;
    cudaGetSymbolAddress((void**)&h,   g_h);
    cudaGetSymbolAddress((void**)&q,   g_q);
    cudaGetSymbolAddress((void**)&k,   g_k);
    cudaGetSymbolAddress((void**)&v,   g_v);
    cudaGetSymbolAddress((void**)&att, g_att);
    cudaGetSymbolAddress((void**)&x1,  g_x1);
    cudaGetSymbolAddress((void**)&ff,  g_ff);

    cudaFuncSetAttribute((const void*)flash_kernel,
                         cudaFuncAttributeMaxDynamicSharedMemorySize,
                         FLASH_SMEM_BYTES);

    // 1) h = LN1(x)   (padding mask provably unnecessary here; see analysis)
    ln_kernel<<<MTOT, 256>>>(x, ln1w, ln1b, h);

    // 2) q,k,v = h @ W  (weight [C,H,D] row-major == [C,C] with col=h*64+d)
    dim3 gQKV(CEMB / 128, MTOT / 128);
    sgemm_kernel<0><<<gQKV, 256>>>(h, wq, q, nullptr, nullptr, nullptr, MTOT, CEMB, CEMB);
    sgemm_kernel<0><<<gQKV, 256>>>(h, wk, k, nullptr, nullptr, nullptr, MTOT, CEMB, CEMB);
    sgemm_kernel<0><<<gQKV, 256>>>(h, wv, v, nullptr, nullptr, nullptr, MTOT, CEMB, CEMB);

    // 3) causal flash attention
    flash_kernel<<<dim3(TSEQ / 64, 4 * 16), 256, FLASH_SMEM_BYTES>>>(q, k, v, att);

    // 4) x1 = x + att @ proj_w + proj_b
    sgemm_kernel<1><<<gQKV, 256>>>(att, proj_w, x1, x, proj_b, nullptr, MTOT, CEMB, CEMB);

    // 5) h = LN2(x1)
    ln_kernel<<<MTOT, 256>>>(x1, ln2w, ln2b, h);

    // 6) ff = relu(h @ W1 + b1)
    dim3 gFF1(DFF / 128, MTOT / 128);
    sgemm_kernel<2><<<gFF1, 256>>>(h, ff_w1, ff, nullptr, ff_b1, nullptr, MTOT, DFF, CEMB);

    // 7) out = (x1 + ff @ W2 + b2) * mask(row)
    sgemm_kernel<3><<<gQKV, 256>>>(ff, ff_w2, out, x1, ff_b2, mask, MTOT, CEMB, DFF);
}

// round 11
// speedup vs baseline: 3.6349x; 3.6349x over previous
#include <cuda_runtime.h>
#include <cuda_bf16.h>
#include <cstdint>
#include <math.h>

// Problem constants
#define TSEQ 2048
#define CEMB 1024
#define MTOT 8192   // B*T
#define DFF  4096

// ---------------- scratch (device globals; no allocation allowed) ------------
__device__ float g_q [(size_t)MTOT * CEMB];
__device__ float g_k [(size_t)MTOT * CEMB];
__device__ float g_v [(size_t)MTOT * CEMB];
__device__ float g_x1[(size_t)MTOT * CEMB];

__device__ __nv_bfloat16 g_hhi[(size_t)MTOT * CEMB];
__device__ __nv_bfloat16 g_hlo[(size_t)MTOT * CEMB];
__device__ __nv_bfloat16 g_ahi[(size_t)MTOT * CEMB];
__device__ __nv_bfloat16 g_alo[(size_t)MTOT * CEMB];
__device__ __nv_bfloat16 g_fhi[(size_t)MTOT * DFF];
__device__ __nv_bfloat16 g_flo[(size_t)MTOT * DFF];

// transposed+split weights: B[n][k] = W[k][n]
__device__ __nv_bfloat16 g_wqh[(size_t)CEMB * CEMB];
__device__ __nv_bfloat16 g_wql[(size_t)CEMB * CEMB];
__device__ __nv_bfloat16 g_wkh[(size_t)CEMB * CEMB];
__device__ __nv_bfloat16 g_wkl[(size_t)CEMB * CEMB];
__device__ __nv_bfloat16 g_wvh[(size_t)CEMB * CEMB];
__device__ __nv_bfloat16 g_wvl[(size_t)CEMB * CEMB];
__device__ __nv_bfloat16 g_wph[(size_t)CEMB * CEMB];
__device__ __nv_bfloat16 g_wpl[(size_t)CEMB * CEMB];
__device__ __nv_bfloat16 g_w1h[(size_t)DFF * CEMB];
__device__ __nv_bfloat16 g_w1l[(size_t)DFF * CEMB];
__device__ __nv_bfloat16 g_w2h[(size_t)CEMB * DFF];
__device__ __nv_bfloat16 g_w2l[(size_t)CEMB * DFF];

// ---------------- helpers (baseline ISA only: sm_80-level PTX) ---------------
__device__ __forceinline__ uint32_t smem_u32(const void* p) {
    uint32_t a;
    asm("{ .reg .u64 t; cvta.to.shared.u64 t, %1; cvt.u32.u64 %0, t; }" : "=r"(a) : "l"(p));
    return a;
}
__device__ __forceinline__ void cp16(uint32_t dst, const void* src) {
    asm volatile("cp.async.cg.shared.global [%0], [%1], 16;" :: "r"(dst), "l"(src));
}
__device__ __forceinline__ void ldsm4(uint32_t* r, uint32_t addr) {
    asm volatile("ldmatrix.sync.aligned.m8n8.x4.shared.b16 {%0,%1,%2,%3}, [%4];"
        : "=r"(r[0]), "=r"(r[1]), "=r"(r[2]), "=r"(r[3]) : "r"(addr));
}
__device__ __forceinline__ void mma16816(float* c, const uint32_t* a, const uint32_t* b) {
    asm volatile("mma.sync.aligned.m16n8k16.row.col.f32.bf16.bf16.f32 "
        "{%0,%1,%2,%3}, {%4,%5,%6,%7}, {%8,%9}, {%0,%1,%2,%3};"
        : "+f"(c[0]), "+f"(c[1]), "+f"(c[2]), "+f"(c[3])
        : "r"(a[0]), "r"(a[1]), "r"(a[2]), "r"(a[3]), "r"(b[0]), "r"(b[1]));
}
#define SWZ(x) ((x) ^ (((x) >> 3) & 0x70))

// ---------------- LayerNorm -> bf16 hi/lo ------------------------------------
__global__ __launch_bounds__(256)
void ln_kernel(const float* __restrict__ x, const float* __restrict__ w,
               const float* __restrict__ bb,
               __nv_bfloat16* __restrict__ ohi, __nv_bfloat16* __restrict__ olo)
{
    __shared__ float sred[8];
    __shared__ float s_mu, s_var;
    const int row = blockIdx.x;
    const int tid = threadIdx.x;

    float4 v = ((const float4*)(x + (size_t)row * CEMB))[tid];
    float s = v.x + v.y + v.z + v.w;
    #pragma unroll
    for (int o = 16; o > 0; o >>= 1) s += __shfl_down_sync(0xffffffffu, s, o);
    if ((tid & 31) == 0) sred[tid >> 5] = s;
    __syncthreads();
    if (tid == 0) {
        float t = 0.f;
        #pragma unroll
        for (int i = 0; i < 8; i++) t += sred[i];
        s_mu = t * (1.f / 1024.f);
    }
    __syncthreads();
    const float mu = s_mu;
    float a0 = v.x - mu, a1 = v.y - mu, a2 = v.z - mu, a3 = v.w - mu;
    float sq = a0 * a0 + a1 * a1 + a2 * a2 + a3 * a3;
    #pragma unroll
    for (int o = 16; o > 0; o >>= 1) sq += __shfl_down_sync(0xffffffffu, sq, o);
    if ((tid & 31) == 0) sred[tid >> 5] = sq;
    __syncthreads();
    if (tid == 0) {
        float t = 0.f;
        #pragma unroll
        for (int i = 0; i < 8; i++) t += sred[i];
        s_var = t * (1.f / 1024.f);
    }
    __syncthreads();
    const float r = rsqrtf(s_var + 1e-5f);
    float4 wv = ((const float4*)w)[tid];
    float4 bv = ((const float4*)bb)[tid];
    float o0 = a0 * r * wv.x + bv.x;
    float o1 = a1 * r * wv.y + bv.y;
    float o2 = a2 * r * wv.z + bv.z;
    float o3 = a3 * r * wv.w + bv.w;
    __nv_bfloat16 h0 = __float2bfloat16(o0), h1 = __float2bfloat16(o1);
    __nv_bfloat16 h2 = __float2bfloat16(o2), h3 = __float2bfloat16(o3);
    __nv_bfloat16 l0 = __float2bfloat16(o0 - __bfloat162float(h0));
    __nv_bfloat16 l1 = __float2bfloat16(o1 - __bfloat162float(h1));
    __nv_bfloat16 l2 = __float2bfloat16(o2 - __bfloat162float(h2));
    __nv_bfloat16 l3 = __float2bfloat16(o3 - __bfloat162float(h3));
    const size_t base = (size_t)row * CEMB + tid * 4;
    ((__nv_bfloat162*)(ohi + base))[0] = __nv_bfloat162(h0, h1);
    ((__nv_bfloat162*)(ohi + base))[1] = __nv_bfloat162(h2, h3);
    ((__nv_bfloat162*)(olo + base))[0] = __nv_bfloat162(l0, l1);
    ((__nv_bfloat162*)(olo + base))[1] = __nv_bfloat162(l2, l3);
}

// ---------------- weight transpose + split: W[K,N] -> B{hi,lo}[N,K] ----------
__global__ __launch_bounds__(256)
void wconv_kernel(const float* __restrict__ W, __nv_bfloat16* __restrict__ Bh,
                  __nv_bfloat16* __restrict__ Bl, int K, int N)
{
    __shared__ float t[32][33];
    const int tx = threadIdx.x & 31, ty = threadIdx.x >> 5;
    const int n0 = blockIdx.x * 32, k0 = blockIdx.y * 32;
    #pragma unroll
    for (int r = 0; r < 32; r += 8)
        t[ty + r][tx] = W[(size_t)(k0 + ty + r) * N + n0 + tx];
    __syncthreads();
    #pragma unroll
    for (int r = 0; r < 32; r += 8) {
        float w = t[tx][ty + r];
        __nv_bfloat16 h = __float2bfloat16(w);
        __nv_bfloat16 l = __float2bfloat16(w - __bfloat162float(h));
        const size_t o = (size_t)(n0 + ty + r) * K + k0 + tx;
        Bh[o] = h;
        Bl[o] = l;
    }
}

// ---------------- tensor-core GEMM (mma.sync bf16x3): C = A @ B^T ------------
// A[M,K] hi/lo bf16, B stored [N,K] hi/lo bf16.  fp32 accumulate in registers.
// CTA tile 128x128, 8 warps (2 rows x 4 cols), warp tile 64x32.
// K-stage 64, double-buffered SMEM with SW128 swizzle, cp.async pipeline.
// MODE 0: Cf = acc
// MODE 1: Cf = Rg + acc + bias
// MODE 2: (Chi,Clo) = split(relu(acc + bias))
// MODE 3: Cf = (Rg + acc + bias) * mask(row)
#define STAGE_BYTES 65536                 // Ahi 16K | Alo 16K | Bhi 16K | Blo 16K
#define GEMM_SMEM   (2 * STAGE_BYTES)

template<int MODE>
__global__ __launch_bounds__(256, 1)
void tgemm_kernel(const __nv_bfloat16* __restrict__ Ahi, const __nv_bfloat16* __restrict__ Alo,
                  const __nv_bfloat16* __restrict__ Bhi, const __nv_bfloat16* __restrict__ Blo,
                  float* __restrict__ Cf, __nv_bfloat16* __restrict__ Chi,
                  __nv_bfloat16* __restrict__ Clo,
                  const float* __restrict__ Rg, const float* __restrict__ biasg,
                  const unsigned char* __restrict__ maskg, int M, int N, int K)
{
    extern __shared__ char smem[];
    const uint32_t sb = smem_u32(smem);
    const int tid    = threadIdx.x;
    const int lane   = tid & 31;
    const int wid    = tid >> 5;
    const int warp_m = wid & 1;    // 2 x 64 rows
    const int warp_n = wid >> 1;   // 4 x 32 cols
    const int brow   = blockIdx.y * 128;
    const int bcol   = blockIdx.x * 128;

    const __nv_bfloat16* gsub[4] = {
        Ahi + (size_t)brow * K, Alo + (size_t)brow * K,
        Bhi + (size_t)bcol * K, Blo + (size_t)bcol * K };

    float acc[4][4][4];
    #pragma unroll
    for (int m = 0; m < 4; m++)
        #pragma unroll
        for (int nt = 0; nt < 4; nt++)
            #pragma unroll
            for (int e = 0; e < 4; e++) acc[m][nt][e] = 0.f;

    // per-lane ldmatrix row/chunk components
    const int a_row_l = (lane & 15);
    const int a_kh    = lane >> 4;
    const int b_row_l = ((lane >> 4) & 1) * 8 + (lane & 7);
    const int b_kh    = (lane >> 3) & 1;

#define LOAD_STAGE(KT) do {                                                        \
        const uint32_t st_ = sb + ((KT) & 1) * STAGE_BYTES;                        \
        const int k0_ = (KT) * 64;                                                 \
        _Pragma("unroll")                                                          \
        for (int sub = 0; sub < 4; sub++) {                                        \
            const __nv_bfloat16* g_ = gsub[sub];                                   \
            _Pragma("unroll")                                                      \
            for (int c = 0; c < 4; c++) {                                          \
                const int lin = tid + c * 256;                                     \
                const int row = lin >> 3, ch = lin & 7;                            \
                cp16(st_ + sub * 16384 + SWZ(row * 128 + ch * 16),                 \
                     g_ + (size_t)row * K + k0_ + ch * 8);                         \
            }                                                                      \
        }                                                                          \
        asm volatile("cp.async.commit_group;" ::: "memory");                       \
    } while (0)

    const int NKT = K >> 6;
    LOAD_STAGE(0);

    for (int kt = 0; kt < NKT; kt++) {
        if (kt + 1 < NKT) LOAD_STAGE(kt + 1);
        if (kt + 1 < NKT) asm volatile("cp.async.wait_group 1;" ::: "memory");
        else              asm volatile("cp.async.wait_group 0;" ::: "memory");
        __syncthreads();

        const uint32_t st = sb + (kt & 1) * STAGE_BYTES;
        #pragma unroll
        for (int kk = 0; kk < 4; kk++) {
            uint32_t ah[4][4], al[4][4];
            #pragma unroll
            for (int m = 0; m < 4; m++) {
                const uint32_t off = SWZ((warp_m * 64 + m * 16 + a_row_l) * 128
                                         + (2 * kk + a_kh) * 16);
                ldsm4(ah[m], st + off);
                ldsm4(al[m], st + 16384 + off);
            }
            uint32_t bh[2][4], bl[2][4];
            #pragma unroll
            for (int bt = 0; bt < 2; bt++) {
                const uint32_t off = SWZ((warp_n * 32 + bt * 16 + b_row_l) * 128
                                         + (2 * kk + b_kh) * 16);
                ldsm4(bh[bt], st + 32768 + off);
                ldsm4(bl[bt], st + 49152 + off);
            }
            #pragma unroll
            for (int m = 0; m < 4; m++)
                #pragma unroll
                for (int bt = 0; bt < 2; bt++)
                    #pragma unroll
                    for (int half = 0; half < 2; half++) {
                        const int nt = bt * 2 + half;
                        mma16816(acc[m][nt], ah[m], &bh[bt][half * 2]);
                        mma16816(acc[m][nt], ah[m], &bl[bt][half * 2]);
                        mma16816(acc[m][nt], al[m], &bh[bt][half * 2]);
                    }
        }
        __syncthreads();
    }
#undef LOAD_STAGE

    // ---------------- epilogue ----------------
    unsigned int probe = 0;
    if (MODE == 3) probe = (unsigned int)maskg[1];  // t=1 always valid (len>=1024)

    const int rbase = brow + warp_m * 64 + (lane >> 2);
    const int cbase = bcol + warp_n * 32 + (lane & 3) * 2;

    #pragma unroll
    for (int m = 0; m < 4; m++) {
        const size_t rowA = (size_t)(rbase + m * 16);
        const size_t rowB = rowA + 8;
        float mA = 1.f, mB = 1.f;
        if (MODE == 3) {
            mA = probe ? (maskg[rowA] ? 1.f : 0.f)
                       : (((const unsigned int*)maskg)[rowA] ? 1.f : 0.f);
            mB = probe ? (maskg[rowB] ? 1.f : 0.f)
                       : (((const unsigned int*)maskg)[rowB] ? 1.f : 0.f);
        }
        #pragma unroll
        for (int nt = 0; nt < 4; nt++) {
            const int col = cbase + nt * 8;
            float o0 = acc[m][nt][0], o1 = acc[m][nt][1];   // rowA
            float o2 = acc[m][nt][2], o3 = acc[m][nt][3];   // rowB
            if (MODE == 1 || MODE == 3) {
                float2 rA = *(const float2*)(Rg + rowA * N + col);
                float2 rB = *(const float2*)(Rg + rowB * N + col);
                o0 += rA.x; o1 += rA.y; o2 += rB.x; o3 += rB.y;
            }
            if (MODE >= 1) {
                float2 bv = *(const float2*)(biasg + col);
                o0 += bv.x; o1 += bv.y; o2 += bv.x; o3 += bv.y;
            }
            if (MODE == 2) {
                o0 = fmaxf(o0, 0.f); o1 = fmaxf(o1, 0.f);
                o2 = fmaxf(o2, 0.f); o3 = fmaxf(o3, 0.f);
                __nv_bfloat16 h0 = __float2bfloat16(o0), h1 = __float2bfloat16(o1);
                __nv_bfloat16 h2 = __float2bfloat16(o2), h3 = __float2bfloat16(o3);
                __nv_bfloat16 l0 = __float2bfloat16(o0 - __bfloat162float(h0));
                __nv_bfloat16 l1 = __float2bfloat16(o1 - __bfloat162float(h1));
                __nv_bfloat16 l2 = __float2bfloat16(o2 - __bfloat162float(h2));
                __nv_bfloat16 l3 = __float2bfloat16(o3 - __bfloat162float(h3));
                *(__nv_bfloat162*)(Chi + rowA * N + col) = __nv_bfloat162(h0, h1);
                *(__nv_bfloat162*)(Chi + rowB * N + col) = __nv_bfloat162(h2, h3);
                *(__nv_bfloat162*)(Clo + rowA * N + col) = __nv_bfloat162(l0, l1);
                *(__nv_bfloat162*)(Clo + rowB * N + col) = __nv_bfloat162(l2, l3);
            } else {
                if (MODE == 3) { o0 *= mA; o1 *= mA; o2 *= mB; o3 *= mB; }
                *(float2*)(Cf + rowA * N + col) = make_float2(o0, o1);
                *(float2*)(Cf + rowB * N + col) = make_float2(o2, o3);
            }
        }
    }
}

// ---------------- Flash attention (causal), fp32, bf16 hi/lo output ----------
#define FPAD 65
#define FLASH_SMEM_FLOATS (3 * 64 * FPAD + 64 * 16 + 3 * 64)
#define FLASH_SMEM_BYTES  (FLASH_SMEM_FLOATS * 4)

__global__ __launch_bounds__(256)
void flash_kernel(const float* __restrict__ q, const float* __restrict__ k,
                  const float* __restrict__ v,
                  __nv_bfloat16* __restrict__ ohi, __nv_bfloat16* __restrict__ olo)
{
    extern __shared__ float sm[];
    float* Qs    = sm;
    float* KP    = sm + 64 * FPAD;
    float* Vs    = sm + 2 * 64 * FPAD;
    float* red   = sm + 3 * 64 * FPAD;
    float* row_m = red + 64 * 16;
    float* row_l = row_m + 64;
    float* row_a = row_l + 64;

    const int qt  = blockIdx.x;
    const int bh  = blockIdx.y;
    const int bb  = bh >> 4;
    const int h   = bh & 15;
    const int tid = threadIdx.x;
    const int ty  = (tid >> 4) * 4;
    const int tx  = (tid & 15) * 4;
    const size_t rowbase = (size_t)bb * TSEQ;
    const int hoff = h * 64;
    const float NEG = __int_as_float(0xff800000);

    for (int idx = tid; idx < 1024; idx += 256) {
        const int r  = idx >> 4;
        const int d4 = (idx & 15) * 4;
        float4 qv = *(const float4*)(q + (rowbase + (size_t)qt * 64 + r) * CEMB + hoff + d4);
        float* dst = Qs + r * FPAD + d4;
        dst[0] = qv.x; dst[1] = qv.y; dst[2] = qv.z; dst[3] = qv.w;
    }
    if (tid < 64) { row_m[tid] = NEG; row_l[tid] = 0.f; }

    float acc[4][4];
    #pragma unroll
    for (int i = 0; i < 4; i++)
        #pragma unroll
        for (int j = 0; j < 4; j++) acc[i][j] = 0.f;

    for (int jt = 0; jt <= qt; jt++) {
        for (int idx = tid; idx < 1024; idx += 256) {
            const int r  = idx >> 4;
            const int d4 = (idx & 15) * 4;
            const size_t gr = (rowbase + (size_t)jt * 64 + r) * CEMB + hoff + d4;
            float4 kv = *(const float4*)(k + gr);
            float* kd = KP + r * FPAD + d4;
            kd[0] = kv.x; kd[1] = kv.y; kd[2] = kv.z; kd[3] = kv.w;
            float4 vv = *(const float4*)(v + gr);
            float* vd = Vs + r * FPAD + d4;
            vd[0] = vv.x; vd[1] = vv.y; vd[2] = vv.z; vd[3] = vv.w;
        }
        __syncthreads();

        float sc[4][4];
        #pragma unroll
        for (int i = 0; i < 4; i++)
            #pragma unroll
            for (int j = 0; j < 4; j++) sc[i][j] = 0.f;
        #pragma unroll 16
        for (int d = 0; d < 64; d++) {
            float ra[4], rb[4];
            #pragma unroll
            for (int i = 0; i < 4; i++) ra[i] = Qs[(ty + i) * FPAD + d];
            #pragma unroll
            for (int j = 0; j < 4; j++) rb[j] = KP[(tx + j) * FPAD + d];
            #pragma unroll
            for (int i = 0; i < 4; i++)
                #pragma unroll
                for (int j = 0; j < 4; j++)
                    sc[i][j] = fmaf(ra[i], rb[j], sc[i][j]);
        }
        const float scale = 0.03125f;
        #pragma unroll
        for (int i = 0; i < 4; i++)
            #pragma unroll
            for (int j = 0; j < 4; j++) {
                float val = sc[i][j] * scale;
                if (jt == qt && (tx + j) > (ty + i)) val = -1e30f;
                sc[i][j] = val;
            }

        #pragma unroll
        for (int i = 0; i < 4; i++) {
            float mx = fmaxf(fmaxf(sc[i][0], sc[i][1]), fmaxf(sc[i][2], sc[i][3]));
            red[(ty + i) * 16 + (tid & 15)] = mx;
        }
        __syncthreads();
        if (tid < 64) {
            float mx = red[tid * 16];
            #pragma unroll
            for (int kk = 1; kk < 16; kk++) mx = fmaxf(mx, red[tid * 16 + kk]);
            const float mo = row_m[tid];
            const float mn = fmaxf(mo, mx);
            row_a[tid] = __expf(mo - mn);
            row_m[tid] = mn;
        }
        __syncthreads();

        #pragma unroll
        for (int i = 0; i < 4; i++) {
            const float mr = row_m[ty + i];
            float s0 = 0.f;
            #pragma unroll
            for (int j = 0; j < 4; j++) {
                const float p = __expf(sc[i][j] - mr);
                KP[(tx + j) * FPAD + (ty + i)] = p;
                s0 += p;
            }
            red[(ty + i) * 16 + (tid & 15)] = s0;
        }
        __syncthreads();
        if (tid < 64) {
            float s0 = red[tid * 16];
            #pragma unroll
            for (int kk = 1; kk < 16; kk++) s0 += red[tid * 16 + kk];
            row_l[tid] = row_l[tid] * row_a[tid] + s0;
        }
        #pragma unroll
        for (int i = 0; i < 4; i++) {
            const float a = row_a[ty + i];
            #pragma unroll
            for (int j = 0; j < 4; j++) acc[i][j] *= a;
        }
        #pragma unroll 16
        for (int s = 0; s < 64; s++) {
            float rp[4], rv[4];
            #pragma unroll
            for (int i = 0; i < 4; i++) rp[i] = KP[s * FPAD + (ty + i)];
            #pragma unroll
            for (int j = 0; j < 4; j++) rv[j] = Vs[s * FPAD + (tx + j)];
            #pragma unroll
            for (int i = 0; i < 4; i++)
                #pragma unroll
                for (int j = 0; j < 4; j++)
                    acc[i][j] = fmaf(rp[i], rv[j], acc[i][j]);
        }
        __syncthreads();
    }

    #pragma unroll
    for (int i = 0; i < 4; i++) {
        const float inv = 1.f / row_l[ty + i];
        float o0 = acc[i][0] * inv, o1 = acc[i][1] * inv;
        float o2 = acc[i][2] * inv, o3 = acc[i][3] * inv;
        __nv_bfloat16 h0 = __float2bfloat16(o0), h1 = __float2bfloat16(o1);
        __nv_bfloat16 h2 = __float2bfloat16(o2), h3 = __float2bfloat16(o3);
        __nv_bfloat16 l0 = __float2bfloat16(o0 - __bfloat162float(h0));
        __nv_bfloat16 l1 = __float2bfloat16(o1 - __bfloat162float(h1));
        __nv_bfloat16 l2 = __float2bfloat16(o2 - __bfloat162float(h2));
        __nv_bfloat16 l3 = __float2bfloat16(o3 - __bfloat162float(h3));
        const size_t base = (rowbase + (size_t)qt * 64 + ty + i) * CEMB + hoff + tx;
        ((__nv_bfloat162*)(ohi + base))[0] = __nv_bfloat162(h0, h1);
        ((__nv_bfloat162*)(ohi + base))[1] = __nv_bfloat162(h2, h3);
        ((__nv_bfloat162*)(olo + base))[0] = __nv_bfloat162(l0, l1);
        ((__nv_bfloat162*)(olo + base))[1] = __nv_bfloat162(l2, l3);
    }
}

// ---------------- launcher ---------------------------------------------------
extern "C" void kernel_launch(void* const* d_in, const int* in_sizes, int n_in,
                              void* d_out, int out_size)
{
    const float* x      = (const float*)d_in[0];
    const unsigned char* mask = (const unsigned char*)d_in[1];
    const float* wq     = (const float*)d_in[2];
    const float* wk     = (const float*)d_in[3];
    const float* wv     = (const float*)d_in[4];
    const float* proj_w = (const float*)d_in[5];
    const float* proj_b = (const float*)d_in[6];
    const float* ff_w1  = (const float*)d_in[7];
    const float* ff_b1  = (const float*)d_in[8];
    const float* ff_w2  = (const float*)d_in[9];
    const float* ff_b2  = (const float*)d_in[10];
    const float* ln1w   = (const float*)d_in[11];
    const float* ln1b   = (const float*)d_in[12];
    const float* ln2w   = (const float*)d_in[13];
    const float* ln2b   = (const float*)d_in[14];
    float* out = (float*)d_out;

    float *q, *k, *v, *x1;
    __nv_bfloat16 *hhi, *hlo, *ahi, *alo, *fhi, *flo;
    __nv_bfloat16 *wqh, *wql, *wkh, *wkl, *wvh, *wvl, *wph, *wpl, *w1h, *w1l, *w2h, *w2l;
    cudaGetSymbolAddress((void**)&q,   g_q);
    cudaGetSymbolAddress((void**)&k,   g_k);
    cudaGetSymbolAddress((void**)&v,   g_v);
    cudaGetSymbolAddress((void**)&x1,  g_x1);
    cudaGetSymbolAddress((void**)&hhi, g_hhi);
    cudaGetSymbolAddress((void**)&hlo, g_hlo);
    cudaGetSymbolAddress((void**)&ahi, g_ahi);
    cudaGetSymbolAddress((void**)&alo, g_alo);
    cudaGetSymbolAddress((void**)&fhi, g_fhi);
    cudaGetSymbolAddress((void**)&flo, g_flo);
    cudaGetSymbolAddress((void**)&wqh, g_wqh);
    cudaGetSymbolAddress((void**)&wql, g_wql);
    cudaGetSymbolAddress((void**)&wkh, g_wkh);
    cudaGetSymbolAddress((void**)&wkl, g_wkl);
    cudaGetSymbolAddress((void**)&wvh, g_wvh);
    cudaGetSymbolAddress((void**)&wvl, g_wvl);
    cudaGetSymbolAddress((void**)&wph, g_wph);
    cudaGetSymbolAddress((void**)&wpl, g_wpl);
    cudaGetSymbolAddress((void**)&w1h, g_w1h);
    cudaGetSymbolAddress((void**)&w1l, g_w1l);
    cudaGetSymbolAddress((void**)&w2h, g_w2h);
    cudaGetSymbolAddress((void**)&w2l, g_w2l);

    cudaFuncSetAttribute((const void*)flash_kernel,
                         cudaFuncAttributeMaxDynamicSharedMemorySize, FLASH_SMEM_BYTES);
    cudaFuncSetAttribute((const void*)tgemm_kernel<0>,
                         cudaFuncAttributeMaxDynamicSharedMemorySize, GEMM_SMEM);
    cudaFuncSetAttribute((const void*)tgemm_kernel<1>,
                         cudaFuncAttributeMaxDynamicSharedMemorySize, GEMM_SMEM);
    cudaFuncSetAttribute((const void*)tgemm_kernel<2>,
                         cudaFuncAttributeMaxDynamicSharedMemorySize, GEMM_SMEM);
    cudaFuncSetAttribute((const void*)tgemm_kernel<3>,
                         cudaFuncAttributeMaxDynamicSharedMemorySize, GEMM_SMEM);

    // weight transpose + bf16 split (deterministic, every launch)
    wconv_kernel<<<dim3(CEMB / 32, CEMB / 32), 256>>>(wq,     wqh, wql, CEMB, CEMB);
    wconv_kernel<<<dim3(CEMB / 32, CEMB / 32), 256>>>(wk,     wkh, wkl, CEMB, CEMB);
    wconv_kernel<<<dim3(CEMB / 32, CEMB / 32), 256>>>(wv,     wvh, wvl, CEMB, CEMB);
    wconv_kernel<<<dim3(CEMB / 32, CEMB / 32), 256>>>(proj_w, wph, wpl, CEMB, CEMB);
    wconv_kernel<<<dim3(DFF / 32,  CEMB / 32), 256>>>(ff_w1,  w1h, w1l, CEMB, DFF);
    wconv_kernel<<<dim3(CEMB / 32, DFF / 32),  256>>>(ff_w2,  w2h, w2l, DFF,  CEMB);

    // 1) h = LN1(x) -> bf16 hi/lo
    ln_kernel<<<MTOT, 256>>>(x, ln1w, ln1b, hhi, hlo);

    // 2) q,k,v = h @ W (fp32 out for flash)
    dim3 gC(CEMB / 128, MTOT / 128);
    tgemm_kernel<0><<<gC, 256, GEMM_SMEM>>>(hhi, hlo, wqh, wql, q, nullptr, nullptr,
                                            nullptr, nullptr, nullptr, MTOT, CEMB, CEMB);
    tgemm_kernel<0><<<gC, 256, GEMM_SMEM>>>(hhi, hlo, wkh, wkl, k, nullptr, nullptr,
                                            nullptr, nullptr, nullptr, MTOT, CEMB, CEMB);
    tgemm_kernel<0><<<gC, 256, GEMM_SMEM>>>(hhi, hlo, wvh, wvl, v, nullptr, nullptr,
                                            nullptr, nullptr, nullptr, MTOT, CEMB, CEMB);

    // 3) causal flash attention -> att hi/lo
    flash_kernel<<<dim3(TSEQ / 64, 4 * 16), 256, FLASH_SMEM_BYTES>>>(q, k, v, ahi, alo);

    // 4) x1 = x + att @ proj_w + proj_b
    tgemm_kernel<1><<<gC, 256, GEMM_SMEM>>>(ahi, alo, wph, wpl, x1, nullptr, nullptr,
                                            x, proj_b, nullptr, MTOT, CEMB, CEMB);

    // 5) h = LN2(x1)
    ln_kernel<<<MTOT, 256>>>(x1, ln2w, ln2b, hhi, hlo);

    // 6) ff = relu(h @ W1 + b1) -> bf16 hi/lo
    tgemm_kernel<2><<<dim3(DFF / 128, MTOT / 128), 256, GEMM_SMEM>>>(
        hhi, hlo, w1h, w1l, nullptr, fhi, flo, nullptr, ff_b1, nullptr, MTOT, DFF, CEMB);

    // 7) out = (x1 + ff @ W2 + b2) * mask(row)
    tgemm_kernel<3><<<gC, 256, GEMM_SMEM>>>(fhi, flo, w2h, w2l, out, nullptr, nullptr,
                                            x1, ff_b2, mask, MTOT, CEMB, DFF);
}

// round 13
// speedup vs baseline: 5.3314x; 1.4667x over previous
#include <cuda_runtime.h>
#include <cuda_bf16.h>
#include <cstdint>
#include <math.h>

// Problem constants
#define TSEQ 2048
#define CEMB 1024
#define MTOT 8192   // B*T
#define DFF  4096

// ---------------- scratch (device globals; no allocation allowed) ------------
__device__ float g_x1[(size_t)MTOT * CEMB];

__device__ __nv_bfloat16 g_hhi[(size_t)MTOT * CEMB];
__device__ __nv_bfloat16 g_hlo[(size_t)MTOT * CEMB];
__device__ __nv_bfloat16 g_qh [(size_t)MTOT * CEMB];
__device__ __nv_bfloat16 g_ql [(size_t)MTOT * CEMB];
__device__ __nv_bfloat16 g_kh [(size_t)MTOT * CEMB];
__device__ __nv_bfloat16 g_kl [(size_t)MTOT * CEMB];
__device__ __nv_bfloat16 g_vh [(size_t)MTOT * CEMB];
__device__ __nv_bfloat16 g_vl [(size_t)MTOT * CEMB];
__device__ __nv_bfloat16 g_ahi[(size_t)MTOT * CEMB];
__device__ __nv_bfloat16 g_alo[(size_t)MTOT * CEMB];
__device__ __nv_bfloat16 g_fhi[(size_t)MTOT * DFF];
__device__ __nv_bfloat16 g_flo[(size_t)MTOT * DFF];

// transposed+split weights: B[n][k] = W[k][n]
__device__ __nv_bfloat16 g_wqh[(size_t)CEMB * CEMB];
__device__ __nv_bfloat16 g_wql[(size_t)CEMB * CEMB];
__device__ __nv_bfloat16 g_wkh[(size_t)CEMB * CEMB];
__device__ __nv_bfloat16 g_wkl[(size_t)CEMB * CEMB];
__device__ __nv_bfloat16 g_wvh[(size_t)CEMB * CEMB];
__device__ __nv_bfloat16 g_wvl[(size_t)CEMB * CEMB];
__device__ __nv_bfloat16 g_wph[(size_t)CEMB * CEMB];
__device__ __nv_bfloat16 g_wpl[(size_t)CEMB * CEMB];
__device__ __nv_bfloat16 g_w1h[(size_t)DFF * CEMB];
__device__ __nv_bfloat16 g_w1l[(size_t)DFF * CEMB];
__device__ __nv_bfloat16 g_w2h[(size_t)CEMB * DFF];
__device__ __nv_bfloat16 g_w2l[(size_t)CEMB * DFF];

// ---------------- helpers (baseline ISA only) --------------------------------
__device__ __forceinline__ uint32_t smem_u32(const void* p) {
    uint32_t a;
    asm("{ .reg .u64 t; cvta.to.shared.u64 t, %1; cvt.u32.u64 %0, t; }" : "=r"(a) : "l"(p));
    return a;
}
__device__ __forceinline__ void cp16(uint32_t dst, const void* src) {
    asm volatile("cp.async.cg.shared.global [%0], [%1], 16;" :: "r"(dst), "l"(src));
}
__device__ __forceinline__ void ldsm4(uint32_t* r, uint32_t addr) {
    asm volatile("ldmatrix.sync.aligned.m8n8.x4.shared.b16 {%0,%1,%2,%3}, [%4];"
        : "=r"(r[0]), "=r"(r[1]), "=r"(r[2]), "=r"(r[3]) : "r"(addr));
}
__device__ __forceinline__ void ldsm4t(uint32_t* r, uint32_t addr) {
    asm volatile("ldmatrix.sync.aligned.m8n8.x4.trans.shared.b16 {%0,%1,%2,%3}, [%4];"
        : "=r"(r[0]), "=r"(r[1]), "=r"(r[2]), "=r"(r[3]) : "r"(addr));
}
__device__ __forceinline__ void mma16816(float* c, const uint32_t* a, const uint32_t* b) {
    asm volatile("mma.sync.aligned.m16n8k16.row.col.f32.bf16.bf16.f32 "
        "{%0,%1,%2,%3}, {%4,%5,%6,%7}, {%8,%9}, {%0,%1,%2,%3};"
        : "+f"(c[0]), "+f"(c[1]), "+f"(c[2]), "+f"(c[3])
        : "r"(a[0]), "r"(a[1]), "r"(a[2]), "r"(a[3]), "r"(b[0]), "r"(b[1]));
}
__device__ __forceinline__ uint32_t pack_bf2(float lo, float hi) {
    __nv_bfloat162 t = __floats2bfloat162_rn(lo, hi);   // x = lo, y = hi
    return *reinterpret_cast<uint32_t*>(&t);
}
#define SWZ(x) ((x) ^ (((x) >> 3) & 0x70))

// ---------------- LayerNorm -> bf16 hi/lo ------------------------------------
__global__ __launch_bounds__(256)
void ln_kernel(const float* __restrict__ x, const float* __restrict__ w,
               const float* __restrict__ bb,
               __nv_bfloat16* __restrict__ ohi, __nv_bfloat16* __restrict__ olo)
{
    __shared__ float sred[8];
    __shared__ float s_mu, s_var;
    const int row = blockIdx.x;
    const int tid = threadIdx.x;

    float4 v = ((const float4*)(x + (size_t)row * CEMB))[tid];
    float s = v.x + v.y + v.z + v.w;
    #pragma unroll
    for (int o = 16; o > 0; o >>= 1) s += __shfl_down_sync(0xffffffffu, s, o);
    if ((tid & 31) == 0) sred[tid >> 5] = s;
    __syncthreads();
    if (tid == 0) {
        float t = 0.f;
        #pragma unroll
        for (int i = 0; i < 8; i++) t += sred[i];
        s_mu = t * (1.f / 1024.f);
    }
    __syncthreads();
    const float mu = s_mu;
    float a0 = v.x - mu, a1 = v.y - mu, a2 = v.z - mu, a3 = v.w - mu;
    float sq = a0 * a0 + a1 * a1 + a2 * a2 + a3 * a3;
    #pragma unroll
    for (int o = 16; o > 0; o >>= 1) sq += __shfl_down_sync(0xffffffffu, sq, o);
    if ((tid & 31) == 0) sred[tid >> 5] = sq;
    __syncthreads();
    if (tid == 0) {
        float t = 0.f;
        #pragma unroll
        for (int i = 0; i < 8; i++) t += sred[i];
        s_var = t * (1.f / 1024.f);
    }
    __syncthreads();
    const float r = rsqrtf(s_var + 1e-5f);
    float4 wv = ((const float4*)w)[tid];
    float4 bv = ((const float4*)bb)[tid];
    float o0 = a0 * r * wv.x + bv.x;
    float o1 = a1 * r * wv.y + bv.y;
    float o2 = a2 * r * wv.z + bv.z;
    float o3 = a3 * r * wv.w + bv.w;
    __nv_bfloat16 h0 = __float2bfloat16(o0), h1 = __float2bfloat16(o1);
    __nv_bfloat16 h2 = __float2bfloat16(o2), h3 = __float2bfloat16(o3);
    __nv_bfloat16 l0 = __float2bfloat16(o0 - __bfloat162float(h0));
    __nv_bfloat16 l1 = __float2bfloat16(o1 - __bfloat162float(h1));
    __nv_bfloat16 l2 = __float2bfloat16(o2 - __bfloat162float(h2));
    __nv_bfloat16 l3 = __float2bfloat16(o3 - __bfloat162float(h3));
    const size_t base = (size_t)row * CEMB + tid * 4;
    ((__nv_bfloat162*)(ohi + base))[0] = __nv_bfloat162(h0, h1);
    ((__nv_bfloat162*)(ohi + base))[1] = __nv_bfloat162(h2, h3);
    ((__nv_bfloat162*)(olo + base))[0] = __nv_bfloat162(l0, l1);
    ((__nv_bfloat162*)(olo + base))[1] = __nv_bfloat162(l2, l3);
}

// ---------------- weight transpose + split: W[K,N] -> B{hi,lo}[N,K] ----------
__global__ __launch_bounds__(256)
void wconv_kernel(const float* __restrict__ W, __nv_bfloat16* __restrict__ Bh,
                  __nv_bfloat16* __restrict__ Bl, int K, int N)
{
    __shared__ float t[32][33];
    const int tx = threadIdx.x & 31, ty = threadIdx.x >> 5;
    const int n0 = blockIdx.x * 32, k0 = blockIdx.y * 32;
    #pragma unroll
    for (int r = 0; r < 32; r += 8)
        t[ty + r][tx] = W[(size_t)(k0 + ty + r) * N + n0 + tx];
    __syncthreads();
    #pragma unroll
    for (int r = 0; r < 32; r += 8) {
        float w = t[tx][ty + r];
        __nv_bfloat16 h = __float2bfloat16(w);
        __nv_bfloat16 l = __float2bfloat16(w - __bfloat162float(h));
        const size_t o = (size_t)(n0 + ty + r) * K + k0 + tx;
        Bh[o] = h;
        Bl[o] = l;
    }
}

// ---------------- tensor-core GEMM (mma.sync bf16x3): C = A @ B^T ------------
// MODE 0: Cf = acc
// MODE 1: Cf = Rg + acc + bias
// MODE 2: (Chi,Clo) = split(relu(acc + bias))
// MODE 3: Cf = (Rg + acc + bias) * mask(row)
// MODE 4: (Chi,Clo) = split(acc)
#define STAGE_BYTES 65536                 // Ahi 16K | Alo 16K | Bhi 16K | Blo 16K
#define GEMM_SMEM   (2 * STAGE_BYTES)

template<int MODE>
__global__ __launch_bounds__(256, 1)
void tgemm_kernel(const __nv_bfloat16* __restrict__ Ahi, const __nv_bfloat16* __restrict__ Alo,
                  const __nv_bfloat16* __restrict__ Bhi, const __nv_bfloat16* __restrict__ Blo,
                  float* __restrict__ Cf, __nv_bfloat16* __restrict__ Chi,
                  __nv_bfloat16* __restrict__ Clo,
                  const float* __restrict__ Rg, const float* __restrict__ biasg,
                  const unsigned char* __restrict__ maskg, int M, int N, int K)
{
    extern __shared__ char smem[];
    const uint32_t sb = smem_u32(smem);
    const int tid    = threadIdx.x;
    const int lane   = tid & 31;
    const int wid    = tid >> 5;
    const int warp_m = wid & 1;    // 2 x 64 rows
    const int warp_n = wid >> 1;   // 4 x 32 cols
    const int brow   = blockIdx.y * 128;
    const int bcol   = blockIdx.x * 128;

    const __nv_bfloat16* gsub[4] = {
        Ahi + (size_t)brow * K, Alo + (size_t)brow * K,
        Bhi + (size_t)bcol * K, Blo + (size_t)bcol * K };

    float acc[4][4][4];
    #pragma unroll
    for (int m = 0; m < 4; m++)
        #pragma unroll
        for (int nt = 0; nt < 4; nt++)
            #pragma unroll
            for (int e = 0; e < 4; e++) acc[m][nt][e] = 0.f;

    const int a_row_l = (lane & 15);
    const int a_kh    = lane >> 4;
    const int b_row_l = ((lane >> 4) & 1) * 8 + (lane & 7);
    const int b_kh    = (lane >> 3) & 1;

#define LOAD_STAGE(KT) do {                                                        \
        const uint32_t st_ = sb + ((KT) & 1) * STAGE_BYTES;                        \
        const int k0_ = (KT) * 64;                                                 \
        _Pragma("unroll")                                                          \
        for (int sub = 0; sub < 4; sub++) {                                        \
            const __nv_bfloat16* g_ = gsub[sub];                                   \
            _Pragma("unroll")                                                      \
            for (int c = 0; c < 4; c++) {                                          \
                const int lin = tid + c * 256;                                     \
                const int row = lin >> 3, ch = lin & 7;                            \
                cp16(st_ + sub * 16384 + SWZ(row * 128 + ch * 16),                 \
                     g_ + (size_t)row * K + k0_ + ch * 8);                         \
            }                                                                      \
        }                                                                          \
        asm volatile("cp.async.commit_group;" ::: "memory");                       \
    } while (0)

    const int NKT = K >> 6;
    LOAD_STAGE(0);

    for (int kt = 0; kt < NKT; kt++) {
        if (kt + 1 < NKT) LOAD_STAGE(kt + 1);
        if (kt + 1 < NKT) asm volatile("cp.async.wait_group 1;" ::: "memory");
        else              asm volatile("cp.async.wait_group 0;" ::: "memory");
        __syncthreads();

        const uint32_t st = sb + (kt & 1) * STAGE_BYTES;
        #pragma unroll
        for (int kk = 0; kk < 4; kk++) {
            uint32_t ah[4][4], al[4][4];
            #pragma unroll
            for (int m = 0; m < 4; m++) {
                const uint32_t off = SWZ((warp_m * 64 + m * 16 + a_row_l) * 128
                                         + (2 * kk + a_kh) * 16);
                ldsm4(ah[m], st + off);
                ldsm4(al[m], st + 16384 + off);
            }
            uint32_t bh[2][4], bl[2][4];
            #pragma unroll
            for (int bt = 0; bt < 2; bt++) {
                const uint32_t off = SWZ((warp_n * 32 + bt * 16 + b_row_l) * 128
                                         + (2 * kk + b_kh) * 16);
                ldsm4(bh[bt], st + 32768 + off);
                ldsm4(bl[bt], st + 49152 + off);
            }
            #pragma unroll
            for (int m = 0; m < 4; m++)
                #pragma unroll
                for (int bt = 0; bt < 2; bt++)
                    #pragma unroll
                    for (int half = 0; half < 2; half++) {
                        const int nt = bt * 2 + half;
                        mma16816(acc[m][nt], ah[m], &bh[bt][half * 2]);
                        mma16816(acc[m][nt], ah[m], &bl[bt][half * 2]);
                        mma16816(acc[m][nt], al[m], &bh[bt][half * 2]);
                    }
        }
        __syncthreads();
    }
#undef LOAD_STAGE

    // ---------------- epilogue ----------------
    unsigned int probe = 0;
    if (MODE == 3) probe = (unsigned int)maskg[1];  // t=1 always valid (len>=1024)

    const int rbase = brow + warp_m * 64 + (lane >> 2);
    const int cbase = bcol + warp_n * 32 + (lane & 3) * 2;

    #pragma unroll
    for (int m = 0; m < 4; m++) {
        const size_t rowA = (size_t)(rbase + m * 16);
        const size_t rowB = rowA + 8;
        float mA = 1.f, mB = 1.f;
        if (MODE == 3) {
            mA = probe ? (maskg[rowA] ? 1.f : 0.f)
                       : (((const unsigned int*)maskg)[rowA] ? 1.f : 0.f);
            mB = probe ? (maskg[rowB] ? 1.f : 0.f)
                       : (((const unsigned int*)maskg)[rowB] ? 1.f : 0.f);
        }
        #pragma unroll
        for (int nt = 0; nt < 4; nt++) {
            const int col = cbase + nt * 8;
            float o0 = acc[m][nt][0], o1 = acc[m][nt][1];   // rowA
            float o2 = acc[m][nt][2], o3 = acc[m][nt][3];   // rowB
            if (MODE == 1 || MODE == 3) {
                float2 rA = *(const float2*)(Rg + rowA * N + col);
                float2 rB = *(const float2*)(Rg + rowB * N + col);
                o0 += rA.x; o1 += rA.y; o2 += rB.x; o3 += rB.y;
            }
            if (MODE == 1 || MODE == 2 || MODE == 3) {
                float2 bv = *(const float2*)(biasg + col);
                o0 += bv.x; o1 += bv.y; o2 += bv.x; o3 += bv.y;
            }
            if (MODE == 2) {
                o0 = fmaxf(o0, 0.f); o1 = fmaxf(o1, 0.f);
                o2 = fmaxf(o2, 0.f); o3 = fmaxf(o3, 0.f);
            }
            if (MODE == 2 || MODE == 4) {
                __nv_bfloat16 h0 = __float2bfloat16(o0), h1 = __float2bfloat16(o1);
                __nv_bfloat16 h2 = __float2bfloat16(o2), h3 = __float2bfloat16(o3);
                __nv_bfloat16 l0 = __float2bfloat16(o0 - __bfloat162float(h0));
                __nv_bfloat16 l1 = __float2bfloat16(o1 - __bfloat162float(h1));
                __nv_bfloat16 l2 = __float2bfloat16(o2 - __bfloat162float(h2));
                __nv_bfloat16 l3 = __float2bfloat16(o3 - __bfloat162float(h3));
                *(__nv_bfloat162*)(Chi + rowA * N + col) = __nv_bfloat162(h0, h1);
                *(__nv_bfloat162*)(Chi + rowB * N + col) = __nv_bfloat162(h2, h3);
                *(__nv_bfloat162*)(Clo + rowA * N + col) = __nv_bfloat162(l0, l1);
                *(__nv_bfloat162*)(Clo + rowB * N + col) = __nv_bfloat162(l2, l3);
            } else {
                if (MODE == 3) { o0 *= mA; o1 *= mA; o2 *= mB; o3 *= mB; }
                *(float2*)(Cf + rowA * N + col) = make_float2(o0, o1);
                *(float2*)(Cf + rowB * N + col) = make_float2(o2, o3);
            }
        }
    }
}

// ---------------- Flash attention (causal), tensor-core bf16x3 ---------------
// grid (T/64, B*H); 128 threads = 4 warps, 16 q-rows per warp, KV tile 64.
// Q fragments in regs; K/V double-buffered smem; S/P fully register-resident.
// smem: Q hi/lo 16KB | stage0 32KB (Kh,Kl,Vh,Vl) | stage1 32KB
#define FL_SMEM (16384 + 2 * 32768)

__global__ __launch_bounds__(128)
void flashtc_kernel(const __nv_bfloat16* __restrict__ qh_, const __nv_bfloat16* __restrict__ ql_,
                    const __nv_bfloat16* __restrict__ kh_, const __nv_bfloat16* __restrict__ kl_,
                    const __nv_bfloat16* __restrict__ vh_, const __nv_bfloat16* __restrict__ vl_,
                    __nv_bfloat16* __restrict__ ohi, __nv_bfloat16* __restrict__ olo)
{
    extern __shared__ char smch[];
    const uint32_t sb = smem_u32(smch);
    const int qt  = blockIdx.x;
    const int bh  = blockIdx.y;
    const int bb  = bh >> 4;
    const int h   = bh & 15;
    const int tid = threadIdx.x;
    const int lane = tid & 31;
    const int w    = tid >> 5;
    const size_t rowbase = (size_t)bb * TSEQ;
    const int hoff = h * 64;

    // fragment lane components
    const int a_row = lane & 15, a_kh = lane >> 4;                    // A (Q) loads
    const int b_row = ((lane >> 4) & 1) * 8 + (lane & 7);             // B (K) loads
    const int b_kh  = (lane >> 3) & 1;
    const int v_row = ((lane >> 3) & 1) * 8 + (lane & 7);             // V trans loads
    const int v_db  = (lane >> 4) * 16;

    // ---- async tile loader: 64 rows x 64 bf16 (128B rows, SW128)
#define LOAD_64x64(gptr, trow, dst) do {                                           \
        _Pragma("unroll")                                                          \
        for (int c = 0; c < 4; c++) {                                              \
            const int idx = tid + c * 128;                                         \
            const int r_ = idx >> 3, ch_ = idx & 7;                                \
            cp16((dst) + SWZ(r_ * 128 + ch_ * 16),                                 \
                 (gptr) + (rowbase + (trow) + r_) * CEMB + hoff + ch_ * 8);        \
        }                                                                          \
    } while (0)
#define LOAD_KV(JT) do {                                                           \
        const uint32_t stb_ = sb + 16384 + ((JT) & 1) * 32768;                     \
        LOAD_64x64(kh_, (JT) * 64, stb_);                                          \
        LOAD_64x64(kl_, (JT) * 64, stb_ + 8192);                                   \
        LOAD_64x64(vh_, (JT) * 64, stb_ + 16384);                                  \
        LOAD_64x64(vl_, (JT) * 64, stb_ + 24576);                                  \
        asm volatile("cp.async.commit_group;" ::: "memory");                       \
    } while (0)

    // Q tile (own async group!) + KV stage 0
    LOAD_64x64(qh_, qt * 64, sb);
    LOAD_64x64(ql_, qt * 64, sb + 8192);
    asm volatile("cp.async.commit_group;" ::: "memory");   // Q = group 0 (FIX)
    LOAD_KV(0);                                            // KV0 = group 1
    asm volatile("cp.async.wait_group 1;" ::: "memory");   // wait Q, KV0 may fly
    __syncthreads();

    // Q fragments (registers)
    uint32_t qfh[4][4], qfl[4][4];
    #pragma unroll
    for (int kk = 0; kk < 4; kk++) {
        const uint32_t off = SWZ((w * 16 + a_row) * 128 + (2 * kk + a_kh) * 16);
        ldsm4(qfh[kk], sb + off);
        ldsm4(qfl[kk], sb + 8192 + off);
    }

    float oacc[8][4];
    #pragma unroll
    for (int nt = 0; nt < 8; nt++)
        #pragma unroll
        for (int e = 0; e < 4; e++) oacc[nt][e] = 0.f;
    float m0 = -1e30f, m1 = -1e30f, l0 = 0.f, l1 = 0.f;

    const int row0 = qt * 64 + w * 16 + (lane >> 2);  // global q row (frag rows)
    const int row1 = row0 + 8;
    const float scale = 0.03125f;  // 1024^-0.5

    for (int jt = 0; jt <= qt; jt++) {
        if (jt + 1 <= qt) {
            LOAD_KV(jt + 1);
            asm volatile("cp.async.wait_group 1;" ::: "memory");
        } else {
            asm volatile("cp.async.wait_group 0;" ::: "memory");
        }
        __syncthreads();

        const uint32_t st = sb + 16384 + (jt & 1) * 32768;

        // ---- S = Q K^T (bf16x3)
        float sacc[8][4];
        #pragma unroll
        for (int nt = 0; nt < 8; nt++)
            #pragma unroll
            for (int e = 0; e < 4; e++) sacc[nt][e] = 0.f;
        #pragma unroll
        for (int kk = 0; kk < 4; kk++) {
            #pragma unroll
            for (int nt2 = 0; nt2 < 4; nt2++) {
                uint32_t kf[4], lf[4];
                const uint32_t off = SWZ((nt2 * 16 + b_row) * 128 + (2 * kk + b_kh) * 16);
                ldsm4(kf, st + off);
                ldsm4(lf, st + 8192 + off);
                #pragma unroll
                for (int half = 0; half < 2; half++) {
                    const int nt = nt2 * 2 + half;
                    mma16816(sacc[nt], qfh[kk], &kf[half * 2]);
                    mma16816(sacc[nt], qfh[kk], &lf[half * 2]);
                    mma16816(sacc[nt], qfl[kk], &kf[half * 2]);
                }
            }
        }

        // ---- scale + causal mask + tile row max
        float tm0 = -1e30f, tm1 = -1e30f;
        #pragma unroll
        for (int nt = 0; nt < 8; nt++) {
            const int col = jt * 64 + nt * 8 + (lane & 3) * 2;
            float s0 = sacc[nt][0] * scale;
            float s1 = sacc[nt][1] * scale;
            float s2 = sacc[nt][2] * scale;
            float s3 = sacc[nt][3] * scale;
            if (jt == qt) {
                if (col     > row0) s0 = -1e30f;
                if (col + 1 > row0) s1 = -1e30f;
                if (col     > row1) s2 = -1e30f;
                if (col + 1 > row1) s3 = -1e30f;
            }
            sacc[nt][0] = s0; sacc[nt][1] = s1; sacc[nt][2] = s2; sacc[nt][3] = s3;
            tm0 = fmaxf(tm0, fmaxf(s0, s1));
            tm1 = fmaxf(tm1, fmaxf(s2, s3));
        }
        tm0 = fmaxf(tm0, __shfl_xor_sync(0xffffffffu, tm0, 1));
        tm0 = fmaxf(tm0, __shfl_xor_sync(0xffffffffu, tm0, 2));
        tm1 = fmaxf(tm1, __shfl_xor_sync(0xffffffffu, tm1, 1));
        tm1 = fmaxf(tm1, __shfl_xor_sync(0xffffffffu, tm1, 2));

        const float mn0 = fmaxf(m0, tm0), mn1 = fmaxf(m1, tm1);
        const float al0 = __expf(m0 - mn0), al1 = __expf(m1 - mn1);
        m0 = mn0; m1 = mn1;

        // ---- P = exp(S - m), row sums
        float rs0 = 0.f, rs1 = 0.f;
        #pragma unroll
        for (int nt = 0; nt < 8; nt++) {
            float p0 = __expf(sacc[nt][0] - mn0);
            float p1 = __expf(sacc[nt][1] - mn0);
            float p2 = __expf(sacc[nt][2] - mn1);
            float p3 = __expf(sacc[nt][3] - mn1);
            sacc[nt][0] = p0; sacc[nt][1] = p1; sacc[nt][2] = p2; sacc[nt][3] = p3;
            rs0 += p0 + p1; rs1 += p2 + p3;
        }
        rs0 += __shfl_xor_sync(0xffffffffu, rs0, 1);
        rs0 += __shfl_xor_sync(0xffffffffu, rs0, 2);
        rs1 += __shfl_xor_sync(0xffffffffu, rs1, 1);
        rs1 += __shfl_xor_sync(0xffffffffu, rs1, 2);
        l0 = l0 * al0 + rs0;
        l1 = l1 * al1 + rs1;

        // ---- rescale O
        #pragma unroll
        for (int nt = 0; nt < 8; nt++) {
            oacc[nt][0] *= al0; oacc[nt][1] *= al0;
            oacc[nt][2] *= al1; oacc[nt][3] *= al1;
        }

        // ---- O += P V (bf16x3); P fragments re-packed from S accumulators
        #pragma unroll
        for (int kk2 = 0; kk2 < 4; kk2++) {
            const int t0 = kk2 * 2, t1 = t0 + 1;
            uint32_t pah[4], pal[4];
            {
                float e0, e1;
                __nv_bfloat16 bh_, bl_;
                e0 = sacc[t0][0]; e1 = sacc[t0][1];
                bh_ = __float2bfloat16(e0);
                bl_ = __float2bfloat16(e1);
                pah[0] = pack_bf2(e0, e1);
                pal[0] = pack_bf2(e0 - __bfloat162float(bh_), e1 - __bfloat162float(bl_));
                e0 = sacc[t0][2]; e1 = sacc[t0][3];
                bh_ = __float2bfloat16(e0);
                bl_ = __float2bfloat16(e1);
                pah[1] = pack_bf2(e0, e1);
                pal[1] = pack_bf2(e0 - __bfloat162float(bh_), e1 - __bfloat162float(bl_));
                e0 = sacc[t1][0]; e1 = sacc[t1][1];
                bh_ = __float2bfloat16(e0);
                bl_ = __float2bfloat16(e1);
                pah[2] = pack_bf2(e0, e1);
                pal[2] = pack_bf2(e0 - __bfloat162float(bh_), e1 - __bfloat162float(bl_));
                e0 = sacc[t1][2]; e1 = sacc[t1][3];
                bh_ = __float2bfloat16(e0);
                bl_ = __float2bfloat16(e1);
                pah[3] = pack_bf2(e0, e1);
                pal[3] = pack_bf2(e0 - __bfloat162float(bh_), e1 - __bfloat162float(bl_));
            }
            #pragma unroll
            for (int nt2 = 0; nt2 < 4; nt2++) {
                uint32_t vh4[4], vl4[4];
                const uint32_t voff = SWZ((kk2 * 16 + v_row) * 128 + nt2 * 32 + v_db);
                ldsm4t(vh4, st + 16384 + voff);
                ldsm4t(vl4, st + 24576 + voff);
                mma16816(oacc[nt2 * 2],     pah, &vh4[0]);
                mma16816(oacc[nt2 * 2],     pah, &vl4[0]);
                mma16816(oacc[nt2 * 2],     pal, &vh4[0]);
                mma16816(oacc[nt2 * 2 + 1], pah, &vh4[2]);
                mma16816(oacc[nt2 * 2 + 1], pah, &vl4[2]);
                mma16816(oacc[nt2 * 2 + 1], pal, &vh4[2]);
            }
        }
        __syncthreads();   // all warps done with this stage before it is reloaded
    }
#undef LOAD_KV
#undef LOAD_64x64

    // ---- epilogue: O / l -> bf16 hi/lo
    const float inv0 = 1.f / l0, inv1 = 1.f / l1;
    const size_t gr0 = (rowbase + (size_t)row0) * CEMB + hoff;
    const size_t gr1 = (rowbase + (size_t)row1) * CEMB + hoff;
    #pragma unroll
    for (int nt = 0; nt < 8; nt++) {
        const int col = nt * 8 + (lane & 3) * 2;
        float o0 = oacc[nt][0] * inv0, o1 = oacc[nt][1] * inv0;
        float o2 = oacc[nt][2] * inv1, o3 = oacc[nt][3] * inv1;
        __nv_bfloat16 h0 = __float2bfloat16(o0), h1 = __float2bfloat16(o1);
        __nv_bfloat16 h2 = __float2bfloat16(o2), h3 = __float2bfloat16(o3);
        __nv_bfloat16 l0b = __float2bfloat16(o0 - __bfloat162float(h0));
        __nv_bfloat16 l1b = __float2bfloat16(o1 - __bfloat162float(h1));
        __nv_bfloat16 l2b = __float2bfloat16(o2 - __bfloat162float(h2));
        __nv_bfloat16 l3b = __float2bfloat16(o3 - __bfloat162float(h3));
        *(__nv_bfloat162*)(ohi + gr0 + col) = __nv_bfloat162(h0, h1);
        *(__nv_bfloat162*)(ohi + gr1 + col) = __nv_bfloat162(h2, h3);
        *(__nv_bfloat162*)(olo + gr0 + col) = __nv_bfloat162(l0b, l1b);
        *(__nv_bfloat162*)(olo + gr1 + col) = __nv_bfloat162(l2b, l3b);
    }
}

// ---------------- launcher ---------------------------------------------------
extern "C" void kernel_launch(void* const* d_in, const int* in_sizes, int n_in,
                              void* d_out, int out_size)
{
    const float* x      = (const float*)d_in[0];
    const unsigned char* mask = (const unsigned char*)d_in[1];
    const float* wq     = (const float*)d_in[2];
    const float* wk     = (const float*)d_in[3];
    const float* wv     = (const float*)d_in[4];
    const float* proj_w = (const float*)d_in[5];
    const float* proj_b = (const float*)d_in[6];
    const float* ff_w1  = (const float*)d_in[7];
    const float* ff_b1  = (const float*)d_in[8];
    const float* ff_w2  = (const float*)d_in[9];
    const float* ff_b2  = (const float*)d_in[10];
    const float* ln1w   = (const float*)d_in[11];
    const float* ln1b   = (const float*)d_in[12];
    const float* ln2w   = (const float*)d_in[13];
    const float* ln2b   = (const float*)d_in[14];
    float* out = (float*)d_out;

    float* x1;
    __nv_bfloat16 *hhi, *hlo, *qh, *ql, *kh, *kl, *vh, *vl, *ahi, *alo, *fhi, *flo;
    __nv_bfloat16 *wqh, *wql, *wkh, *wkl, *wvh, *wvl, *wph, *wpl, *w1h, *w1l, *w2h, *w2l;
    cudaGetSymbolAddress((void**)&x1,  g_x1);
    cudaGetSymbolAddress((void**)&hhi, g_hhi);
    cudaGetSymbolAddress((void**)&hlo, g_hlo);
    cudaGetSymbolAddress((void**)&qh,  g_qh);
    cudaGetSymbolAddress((void**)&ql,  g_ql);
    cudaGetSymbolAddress((void**)&kh,  g_kh);
    cudaGetSymbolAddress((void**)&kl,  g_kl);
    cudaGetSymbolAddress((void**)&vh,  g_vh);
    cudaGetSymbolAddress((void**)&vl,  g_vl);
    cudaGetSymbolAddress((void**)&ahi, g_ahi);
    cudaGetSymbolAddress((void**)&alo, g_alo);
    cudaGetSymbolAddress((void**)&fhi, g_fhi);
    cudaGetSymbolAddress((void**)&flo, g_flo);
    cudaGetSymbolAddress((void**)&wqh, g_wqh);
    cudaGetSymbolAddress((void**)&wql, g_wql);
    cudaGetSymbolAddress((void**)&wkh, g_wkh);
    cudaGetSymbolAddress((void**)&wkl, g_wkl);
    cudaGetSymbolAddress((void**)&wvh, g_wvh);
    cudaGetSymbolAddress((void**)&wvl, g_wvl);
    cudaGetSymbolAddress((void**)&wph, g_wph);
    cudaGetSymbolAddress((void**)&wpl, g_wpl);
    cudaGetSymbolAddress((void**)&w1h, g_w1h);
    cudaGetSymbolAddress((void**)&w1l, g_w1l);
    cudaGetSymbolAddress((void**)&w2h, g_w2h);
    cudaGetSymbolAddress((void**)&w2l, g_w2l);

    cudaFuncSetAttribute((const void*)flashtc_kernel,
                         cudaFuncAttributeMaxDynamicSharedMemorySize, FL_SMEM);
    cudaFuncSetAttribute((const void*)tgemm_kernel<1>,
                         cudaFuncAttributeMaxDynamicSharedMemorySize, GEMM_SMEM);
    cudaFuncSetAttribute((const void*)tgemm_kernel<2>,
                         cudaFuncAttributeMaxDynamicSharedMemorySize, GEMM_SMEM);
    cudaFuncSetAttribute((const void*)tgemm_kernel<3>,
                         cudaFuncAttributeMaxDynamicSharedMemorySize, GEMM_SMEM);
    cudaFuncSetAttribute((const void*)tgemm_kernel<4>,
                         cudaFuncAttributeMaxDynamicSharedMemorySize, GEMM_SMEM);

    // weight transpose + bf16 split (deterministic, every launch)
    wconv_kernel<<<dim3(CEMB / 32, CEMB / 32), 256>>>(wq,     wqh, wql, CEMB, CEMB);
    wconv_kernel<<<dim3(CEMB / 32, CEMB / 32), 256>>>(wk,     wkh, wkl, CEMB, CEMB);
    wconv_kernel<<<dim3(CEMB / 32, CEMB / 32), 256>>>(wv,     wvh, wvl, CEMB, CEMB);
    wconv_kernel<<<dim3(CEMB / 32, CEMB / 32), 256>>>(proj_w, wph, wpl, CEMB, CEMB);
    wconv_kernel<<<dim3(DFF / 32,  CEMB / 32), 256>>>(ff_w1,  w1h, w1l, CEMB, DFF);
    wconv_kernel<<<dim3(CEMB / 32, DFF / 32),  256>>>(ff_w2,  w2h, w2l, DFF,  CEMB);

    // 1) h = LN1(x) -> bf16 hi/lo
    ln_kernel<<<MTOT, 256>>>(x, ln1w, ln1b, hhi, hlo);

    // 2) q,k,v = h @ W -> bf16 hi/lo (MODE 4)
    dim3 gC(CEMB / 128, MTOT / 128);
    tgemm_kernel<4><<<gC, 256, GEMM_SMEM>>>(hhi, hlo, wqh, wql, nullptr, qh, ql,
                                            nullptr, nullptr, nullptr, MTOT, CEMB, CEMB);
    tgemm_kernel<4><<<gC, 256, GEMM_SMEM>>>(hhi, hlo, wkh, wkl, nullptr, kh, kl,
                                            nullptr, nullptr, nullptr, MTOT, CEMB, CEMB);
    tgemm_kernel<4><<<gC, 256, GEMM_SMEM>>>(hhi, hlo, wvh, wvl, nullptr, vh, vl,
                                            nullptr, nullptr, nullptr, MTOT, CEMB, CEMB);

    // 3) causal flash attention (tensor cores) -> att hi/lo
    flashtc_kernel<<<dim3(TSEQ / 64, 4 * 16), 128, FL_SMEM>>>(qh, ql, kh, kl, vh, vl, ahi, alo);

    // 4) x1 = x + att @ proj_w + proj_b
    tgemm_kernel<1><<<gC, 256, GEMM_SMEM>>>(ahi, alo, wph, wpl, x1, nullptr, nullptr,
                                            x, proj_b, nullptr, MTOT, CEMB, CEMB);

    // 5) h = LN2(x1)
    ln_kernel<<<MTOT, 256>>>(x1, ln2w, ln2b, hhi, hlo);

    // 6) ff = relu(h @ W1 + b1) -> bf16 hi/lo
    tgemm_kernel<2><<<dim3(DFF / 128, MTOT / 128), 256, GEMM_SMEM>>>(
        hhi, hlo, w1h, w1l, nullptr, fhi, flo, nullptr, ff_b1, nullptr, MTOT, DFF, CEMB);

    // 7) out = (x1 + ff @ W2 + b2) * mask(row)
    tgemm_kernel<3><<<gC, 256, GEMM_SMEM>>>(fhi, flo, w2h, w2l, out, nullptr, nullptr,
                                            x1, ff_b2, mask, MTOT, CEMB, DFF);
}

// round 15
// speedup vs baseline: 7.7884x; 1.4609x over previous
#include <cuda_runtime.h>
#include <cuda_fp16.h>
#include <cstdint>
#include <math.h>

// Problem constants
#define TSEQ 2048
#define CEMB 1024
#define MTOT 8192   // B*T
#define DFF  4096

// ---------------- scratch (device globals; no allocation allowed) ------------
__device__ float g_x1[(size_t)MTOT * CEMB];

__device__ __half g_h [(size_t)MTOT * CEMB];
__device__ __half g_q [(size_t)MTOT * CEMB];
__device__ __half g_k [(size_t)MTOT * CEMB];
__device__ __half g_v [(size_t)MTOT * CEMB];
__device__ __half g_a [(size_t)MTOT * CEMB];
__device__ __half g_f [(size_t)MTOT * DFF];

// transposed weights: B[n][k] = W[k][n], fp16
__device__ __half g_wq[(size_t)CEMB * CEMB];
__device__ __half g_wk[(size_t)CEMB * CEMB];
__device__ __half g_wv[(size_t)CEMB * CEMB];
__device__ __half g_wp[(size_t)CEMB * CEMB];
__device__ __half g_w1[(size_t)DFF * CEMB];
__device__ __half g_w2[(size_t)CEMB * DFF];

// ---------------- helpers (baseline ISA only) --------------------------------
__device__ __forceinline__ uint32_t smem_u32(const void* p) {
    uint32_t a;
    asm("{ .reg .u64 t; cvta.to.shared.u64 t, %1; cvt.u32.u64 %0, t; }" : "=r"(a) : "l"(p));
    return a;
}
__device__ __forceinline__ void cp16(uint32_t dst, const void* src) {
    asm volatile("cp.async.cg.shared.global [%0], [%1], 16;" :: "r"(dst), "l"(src));
}
__device__ __forceinline__ void ldsm4(uint32_t* r, uint32_t addr) {
    asm volatile("ldmatrix.sync.aligned.m8n8.x4.shared.b16 {%0,%1,%2,%3}, [%4];"
        : "=r"(r[0]), "=r"(r[1]), "=r"(r[2]), "=r"(r[3]) : "r"(addr));
}
__device__ __forceinline__ void ldsm4t(uint32_t* r, uint32_t addr) {
    asm volatile("ldmatrix.sync.aligned.m8n8.x4.trans.shared.b16 {%0,%1,%2,%3}, [%4];"
        : "=r"(r[0]), "=r"(r[1]), "=r"(r[2]), "=r"(r[3]) : "r"(addr));
}
__device__ __forceinline__ void mma16816(float* c, const uint32_t* a, const uint32_t* b) {
    asm volatile("mma.sync.aligned.m16n8k16.row.col.f32.f16.f16.f32 "
        "{%0,%1,%2,%3}, {%4,%5,%6,%7}, {%8,%9}, {%0,%1,%2,%3};"
        : "+f"(c[0]), "+f"(c[1]), "+f"(c[2]), "+f"(c[3])
        : "r"(a[0]), "r"(a[1]), "r"(a[2]), "r"(a[3]), "r"(b[0]), "r"(b[1]));
}
__device__ __forceinline__ uint32_t pack_h2(float a, float b) {
    __half2 t = __floats2half2_rn(a, b);
    return *reinterpret_cast<uint32_t*>(&t);
}
#define SWZ(x) ((x) ^ (((x) >> 3) & 0x70))

// ---------------- LayerNorm -> fp16 ------------------------------------------
__global__ __launch_bounds__(256)
void ln_kernel(const float* __restrict__ x, const float* __restrict__ w,
               const float* __restrict__ bb, __half* __restrict__ oh)
{
    __shared__ float sred[8];
    __shared__ float s_mu, s_var;
    const int row = blockIdx.x;
    const int tid = threadIdx.x;

    float4 v = ((const float4*)(x + (size_t)row * CEMB))[tid];
    float s = v.x + v.y + v.z + v.w;
    #pragma unroll
    for (int o = 16; o > 0; o >>= 1) s += __shfl_down_sync(0xffffffffu, s, o);
    if ((tid & 31) == 0) sred[tid >> 5] = s;
    __syncthreads();
    if (tid == 0) {
        float t = 0.f;
        #pragma unroll
        for (int i = 0; i < 8; i++) t += sred[i];
        s_mu = t * (1.f / 1024.f);
    }
    __syncthreads();
    const float mu = s_mu;
    float a0 = v.x - mu, a1 = v.y - mu, a2 = v.z - mu, a3 = v.w - mu;
    float sq = a0 * a0 + a1 * a1 + a2 * a2 + a3 * a3;
    #pragma unroll
    for (int o = 16; o > 0; o >>= 1) sq += __shfl_down_sync(0xffffffffu, sq, o);
    if ((tid & 31) == 0) sred[tid >> 5] = sq;
    __syncthreads();
    if (tid == 0) {
        float t = 0.f;
        #pragma unroll
        for (int i = 0; i < 8; i++) t += sred[i];
        s_var = t * (1.f / 1024.f);
    }
    __syncthreads();
    const float r = rsqrtf(s_var + 1e-5f);
    float4 wv = ((const float4*)w)[tid];
    float4 bv = ((const float4*)bb)[tid];
    float o0 = a0 * r * wv.x + bv.x;
    float o1 = a1 * r * wv.y + bv.y;
    float o2 = a2 * r * wv.z + bv.z;
    float o3 = a3 * r * wv.w + bv.w;
    const size_t base = (size_t)row * CEMB + tid * 4;
    ((__half2*)(oh + base))[0] = __floats2half2_rn(o0, o1);
    ((__half2*)(oh + base))[1] = __floats2half2_rn(o2, o3);
}

// ---------------- weight transpose: W[K,N] -> B[N,K] fp16 --------------------
__global__ __launch_bounds__(256)
void wconv_kernel(const float* __restrict__ W, __half* __restrict__ Bh, int K, int N)
{
    __shared__ float t[32][33];
    const int tx = threadIdx.x & 31, ty = threadIdx.x >> 5;
    const int n0 = blockIdx.x * 32, k0 = blockIdx.y * 32;
    #pragma unroll
    for (int r = 0; r < 32; r += 8)
        t[ty + r][tx] = W[(size_t)(k0 + ty + r) * N + n0 + tx];
    __syncthreads();
    #pragma unroll
    for (int r = 0; r < 32; r += 8)
        Bh[(size_t)(n0 + ty + r) * K + k0 + tx] = __float2half_rn(t[tx][ty + r]);
}

// ---------------- tensor-core GEMM (mma.sync fp16): C = A @ B^T --------------
// MODE 1: Cf = Rg + acc + bias
// MODE 2: Ch = fp16(relu(acc + bias))
// MODE 3: Cf = (Rg + acc + bias) * mask(row)
// MODE 4: Ch = fp16(acc)
#define STAGE_BYTES 32768                 // A 16K | B 16K
#define NSTAGE      4
#define GEMM_SMEM   (NSTAGE * STAGE_BYTES)

template<int MODE>
__global__ __launch_bounds__(256, 1)
void tgemm_kernel(const __half* __restrict__ Ah, const __half* __restrict__ Bh,
                  float* __restrict__ Cf, __half* __restrict__ Ch,
                  const float* __restrict__ Rg, const float* __restrict__ biasg,
                  const unsigned char* __restrict__ maskg, int M, int N, int K)
{
    extern __shared__ char smem[];
    const uint32_t sb = smem_u32(smem);
    const int tid    = threadIdx.x;
    const int lane   = tid & 31;
    const int wid    = tid >> 5;
    const int warp_m = wid & 1;    // 2 x 64 rows
    const int warp_n = wid >> 1;   // 4 x 32 cols
    const int brow   = blockIdx.y * 128;
    const int bcol   = blockIdx.x * 128;

    const __half* gA = Ah + (size_t)brow * K;
    const __half* gB = Bh + (size_t)bcol * K;

    float acc[4][4][4];
    #pragma unroll
    for (int m = 0; m < 4; m++)
        #pragma unroll
        for (int nt = 0; nt < 4; nt++)
            #pragma unroll
            for (int e = 0; e < 4; e++) acc[m][nt][e] = 0.f;

    const int a_row_l = (lane & 15);
    const int a_kh    = lane >> 4;
    const int b_row_l = ((lane >> 4) & 1) * 8 + (lane & 7);
    const int b_kh    = (lane >> 3) & 1;

    const int NKT = K >> 6;

    // Each stage: A = 128 rows x 128B (16KB) + B = 128 rows x 128B (16KB)
    // => 1024 16B chunks per sub-buffer, 2048 per stage (FIX: was 1024 total)
#define LOAD_STAGE(KT) do {                                                        \
        if ((KT) < NKT) {                                                          \
            const uint32_t st_ = sb + ((KT) % NSTAGE) * STAGE_BYTES;               \
            const int k0_ = (KT) * 64;                                             \
            _Pragma("unroll")                                                      \
            for (int c = 0; c < 4; c++) {                                          \
                const int lin = tid + c * 256;         /* 0..1023 */               \
                const int row = lin >> 3, ch = lin & 7;                            \
                cp16(st_ + SWZ(row * 128 + ch * 16),                               \
                     gA + (size_t)row * K + k0_ + ch * 8);                         \
                cp16(st_ + 16384 + SWZ(row * 128 + ch * 16),                       \
                     gB + (size_t)row * K + k0_ + ch * 8);                         \
            }                                                                      \
        }                                                                          \
        asm volatile("cp.async.commit_group;" ::: "memory");                       \
    } while (0)

    LOAD_STAGE(0);
    LOAD_STAGE(1);
    LOAD_STAGE(2);

    for (int kt = 0; kt < NKT; kt++) {
        asm volatile("cp.async.wait_group 2;" ::: "memory");
        __syncthreads();
        LOAD_STAGE(kt + 3);

        const uint32_t st = sb + (kt % NSTAGE) * STAGE_BYTES;
        #pragma unroll
        for (int kk = 0; kk < 4; kk++) {
            uint32_t ah[4][4];
            #pragma unroll
            for (int m = 0; m < 4; m++) {
                const uint32_t off = SWZ((warp_m * 64 + m * 16 + a_row_l) * 128
                                         + (2 * kk + a_kh) * 16);
                ldsm4(ah[m], st + off);
            }
            uint32_t bh[2][4];
            #pragma unroll
            for (int bt = 0; bt < 2; bt++) {
                const uint32_t off = SWZ((warp_n * 32 + bt * 16 + b_row_l) * 128
                                         + (2 * kk + b_kh) * 16);
                ldsm4(bh[bt], st + 16384 + off);
            }
            #pragma unroll
            for (int m = 0; m < 4; m++)
                #pragma unroll
                for (int bt = 0; bt < 2; bt++)
                    #pragma unroll
                    for (int half = 0; half < 2; half++)
                        mma16816(acc[m][bt * 2 + half], ah[m], &bh[bt][half * 2]);
        }
        __syncthreads();
    }
#undef LOAD_STAGE

    // ---------------- epilogue ----------------
    unsigned int probe = 0;
    if (MODE == 3) probe = (unsigned int)maskg[1];  // t=1 always valid (len>=1024)

    const int rbase = brow + warp_m * 64 + (lane >> 2);
    const int cbase = bcol + warp_n * 32 + (lane & 3) * 2;

    #pragma unroll
    for (int m = 0; m < 4; m++) {
        const size_t rowA = (size_t)(rbase + m * 16);
        const size_t rowB = rowA + 8;
        float mA = 1.f, mB = 1.f;
        if (MODE == 3) {
            mA = probe ? (maskg[rowA] ? 1.f : 0.f)
                       : (((const unsigned int*)maskg)[rowA] ? 1.f : 0.f);
            mB = probe ? (maskg[rowB] ? 1.f : 0.f)
                       : (((const unsigned int*)maskg)[rowB] ? 1.f : 0.f);
        }
        #pragma unroll
        for (int nt = 0; nt < 4; nt++) {
            const int col = cbase + nt * 8;
            float o0 = acc[m][nt][0], o1 = acc[m][nt][1];   // rowA
            float o2 = acc[m][nt][2], o3 = acc[m][nt][3];   // rowB
            if (MODE == 1 || MODE == 3) {
                float2 rA = *(const float2*)(Rg + rowA * N + col);
                float2 rB = *(const float2*)(Rg + rowB * N + col);
                o0 += rA.x; o1 += rA.y; o2 += rB.x; o3 += rB.y;
            }
            if (MODE == 1 || MODE == 2 || MODE == 3) {
                float2 bv = *(const float2*)(biasg + col);
                o0 += bv.x; o1 += bv.y; o2 += bv.x; o3 += bv.y;
            }
            if (MODE == 2) {
                o0 = fmaxf(o0, 0.f); o1 = fmaxf(o1, 0.f);
                o2 = fmaxf(o2, 0.f); o3 = fmaxf(o3, 0.f);
            }
            if (MODE == 2 || MODE == 4) {
                *(__half2*)(Ch + rowA * N + col) = __floats2half2_rn(o0, o1);
                *(__half2*)(Ch + rowB * N + col) = __floats2half2_rn(o2, o3);
            } else {
                if (MODE == 3) { o0 *= mA; o1 *= mA; o2 *= mB; o3 *= mB; }
                *(float2*)(Cf + rowA * N + col) = make_float2(o0, o1);
                *(float2*)(Cf + rowB * N + col) = make_float2(o2, o3);
            }
        }
    }
}

// ---------------- Flash attention (causal), tensor-core fp16 -----------------
// grid (T/64, B*H); 128 threads = 4 warps, 16 q-rows per warp, KV tile 64.
// smem: Q 8KB | stage0 16KB (K,V) | stage1 16KB
#define FL_SMEM (8192 + 2 * 16384)

__global__ __launch_bounds__(128)
void flashtc_kernel(const __half* __restrict__ qh_, const __half* __restrict__ kh_,
                    const __half* __restrict__ vh_, __half* __restrict__ oh_)
{
    extern __shared__ char smch[];
    const uint32_t sb = smem_u32(smch);
    const int qt  = blockIdx.x;
    const int bh  = blockIdx.y;
    const int bb  = bh >> 4;
    const int h   = bh & 15;
    const int tid = threadIdx.x;
    const int lane = tid & 31;
    const int w    = tid >> 5;
    const size_t rowbase = (size_t)bb * TSEQ;
    const int hoff = h * 64;

    const int a_row = lane & 15, a_kh = lane >> 4;
    const int b_row = ((lane >> 4) & 1) * 8 + (lane & 7);
    const int b_kh  = (lane >> 3) & 1;
    const int v_row = ((lane >> 3) & 1) * 8 + (lane & 7);
    const int v_db  = (lane >> 4) * 16;

#define LOAD_64x64(gptr, trow, dst) do {                                           \
        _Pragma("unroll")                                                          \
        for (int c = 0; c < 4; c++) {                                              \
            const int idx = tid + c * 128;                                         \
            const int r_ = idx >> 3, ch_ = idx & 7;                                \
            cp16((dst) + SWZ(r_ * 128 + ch_ * 16),                                 \
                 (gptr) + (rowbase + (trow) + r_) * CEMB + hoff + ch_ * 8);        \
        }                                                                          \
    } while (0)
#define LOAD_KV(JT) do {                                                           \
        const uint32_t stb_ = sb + 8192 + ((JT) & 1) * 16384;                      \
        LOAD_64x64(kh_, (JT) * 64, stb_);                                          \
        LOAD_64x64(vh_, (JT) * 64, stb_ + 8192);                                   \
        asm volatile("cp.async.commit_group;" ::: "memory");                       \
    } while (0)

    // Q tile (own group) + KV stage 0
    LOAD_64x64(qh_, qt * 64, sb);
    asm volatile("cp.async.commit_group;" ::: "memory");
    LOAD_KV(0);
    asm volatile("cp.async.wait_group 1;" ::: "memory");   // Q ready
    __syncthreads();

    uint32_t qf[4][4];
    #pragma unroll
    for (int kk = 0; kk < 4; kk++) {
        const uint32_t off = SWZ((w * 16 + a_row) * 128 + (2 * kk + a_kh) * 16);
        ldsm4(qf[kk], sb + off);
    }

    float oacc[8][4];
    #pragma unroll
    for (int nt = 0; nt < 8; nt++)
        #pragma unroll
        for (int e = 0; e < 4; e++) oacc[nt][e] = 0.f;
    float m0 = -1e30f, m1 = -1e30f, l0 = 0.f, l1 = 0.f;

    const int row0 = qt * 64 + w * 16 + (lane >> 2);
    const int row1 = row0 + 8;
    const float scale = 0.03125f;  // 1024^-0.5

    for (int jt = 0; jt <= qt; jt++) {
        if (jt + 1 <= qt) {
            LOAD_KV(jt + 1);
            asm volatile("cp.async.wait_group 1;" ::: "memory");
        } else {
            asm volatile("cp.async.wait_group 0;" ::: "memory");
        }
        __syncthreads();

        const uint32_t st = sb + 8192 + (jt & 1) * 16384;

        // ---- S = Q K^T
        float sacc[8][4];
        #pragma unroll
        for (int nt = 0; nt < 8; nt++)
            #pragma unroll
            for (int e = 0; e < 4; e++) sacc[nt][e] = 0.f;
        #pragma unroll
        for (int kk = 0; kk < 4; kk++) {
            #pragma unroll
            for (int nt2 = 0; nt2 < 4; nt2++) {
                uint32_t kf[4];
                const uint32_t off = SWZ((nt2 * 16 + b_row) * 128 + (2 * kk + b_kh) * 16);
                ldsm4(kf, st + off);
                mma16816(sacc[nt2 * 2],     qf[kk], &kf[0]);
                mma16816(sacc[nt2 * 2 + 1], qf[kk], &kf[2]);
            }
        }

        // ---- scale + causal mask + tile row max
        float tm0 = -1e30f, tm1 = -1e30f;
        #pragma unroll
        for (int nt = 0; nt < 8; nt++) {
            const int col = jt * 64 + nt * 8 + (lane & 3) * 2;
            float s0 = sacc[nt][0] * scale;
            float s1 = sacc[nt][1] * scale;
            float s2 = sacc[nt][2] * scale;
            float s3 = sacc[nt][3] * scale;
            if (jt == qt) {
                if (col     > row0) s0 = -1e30f;
                if (col + 1 > row0) s1 = -1e30f;
                if (col     > row1) s2 = -1e30f;
                if (col + 1 > row1) s3 = -1e30f;
            }
            sacc[nt][0] = s0; sacc[nt][1] = s1; sacc[nt][2] = s2; sacc[nt][3] = s3;
            tm0 = fmaxf(tm0, fmaxf(s0, s1));
            tm1 = fmaxf(tm1, fmaxf(s2, s3));
        }
        tm0 = fmaxf(tm0, __shfl_xor_sync(0xffffffffu, tm0, 1));
        tm0 = fmaxf(tm0, __shfl_xor_sync(0xffffffffu, tm0, 2));
        tm1 = fmaxf(tm1, __shfl_xor_sync(0xffffffffu, tm1, 1));
        tm1 = fmaxf(tm1, __shfl_xor_sync(0xffffffffu, tm1, 2));

        const float mn0 = fmaxf(m0, tm0), mn1 = fmaxf(m1, tm1);
        const float al0 = __expf(m0 - mn0), al1 = __expf(m1 - mn1);
        m0 = mn0; m1 = mn1;

        // ---- P = exp(S - m), row sums
        float rs0 = 0.f, rs1 = 0.f;
        #pragma unroll
        for (int nt = 0; nt < 8; nt++) {
            float p0 = __expf(sacc[nt][0] - mn0);
            float p1 = __expf(sacc[nt][1] - mn0);
            float p2 = __expf(sacc[nt][2] - mn1);
            float p3 = __expf(sacc[nt][3] - mn1);
            sacc[nt][0] = p0; sacc[nt][1] = p1; sacc[nt][2] = p2; sacc[nt][3] = p3;
            rs0 += p0 + p1; rs1 += p2 + p3;
        }
        rs0 += __shfl_xor_sync(0xffffffffu, rs0, 1);
        rs0 += __shfl_xor_sync(0xffffffffu, rs0, 2);
        rs1 += __shfl_xor_sync(0xffffffffu, rs1, 1);
        rs1 += __shfl_xor_sync(0xffffffffu, rs1, 2);
        l0 = l0 * al0 + rs0;
        l1 = l1 * al1 + rs1;

        // ---- rescale O
        #pragma unroll
        for (int nt = 0; nt < 8; nt++) {
            oacc[nt][0] *= al0; oacc[nt][1] *= al0;
            oacc[nt][2] *= al1; oacc[nt][3] *= al1;
        }

        // ---- O += P V ; P fragments re-packed from S accumulators
        #pragma unroll
        for (int kk2 = 0; kk2 < 4; kk2++) {
            const int t0 = kk2 * 2, t1 = t0 + 1;
            uint32_t pa[4];
            pa[0] = pack_h2(sacc[t0][0], sacc[t0][1]);
            pa[1] = pack_h2(sacc[t0][2], sacc[t0][3]);
            pa[2] = pack_h2(sacc[t1][0], sacc[t1][1]);
            pa[3] = pack_h2(sacc[t1][2], sacc[t1][3]);
            #pragma unroll
            for (int nt2 = 0; nt2 < 4; nt2++) {
                uint32_t v4[4];
                const uint32_t voff = SWZ((kk2 * 16 + v_row) * 128 + nt2 * 32 + v_db);
                ldsm4t(v4, st + 8192 + voff);
                mma16816(oacc[nt2 * 2],     pa, &v4[0]);
                mma16816(oacc[nt2 * 2 + 1], pa, &v4[2]);
            }
        }
        __syncthreads();   // all warps done with this stage before reload
    }
#undef LOAD_KV
#undef LOAD_64x64

    // ---- epilogue: O / l -> fp16
    const float inv0 = 1.f / l0, inv1 = 1.f / l1;
    const size_t gr0 = (rowbase + (size_t)row0) * CEMB + hoff;
    const size_t gr1 = (rowbase + (size_t)row1) * CEMB + hoff;
    #pragma unroll
    for (int nt = 0; nt < 8; nt++) {
        const int col = nt * 8 + (lane & 3) * 2;
        *(__half2*)(oh_ + gr0 + col) = __floats2half2_rn(oacc[nt][0] * inv0, oacc[nt][1] * inv0);
        *(__half2*)(oh_ + gr1 + col) = __floats2half2_rn(oacc[nt][2] * inv1, oacc[nt][3] * inv1);
    }
}

// ---------------- launcher ---------------------------------------------------
extern "C" void kernel_launch(void* const* d_in, const int* in_sizes, int n_in,
                              void* d_out, int out_size)
{
    const float* x      = (const float*)d_in[0];
    const unsigned char* mask = (const unsigned char*)d_in[1];
    const float* wq     = (const float*)d_in[2];
    const float* wk     = (const float*)d_in[3];
    const float* wv     = (const float*)d_in[4];
    const float* proj_w = (const float*)d_in[5];
    const float* proj_b = (const float*)d_in[6];
    const float* ff_w1  = (const float*)d_in[7];
    const float* ff_b1  = (const float*)d_in[8];
    const float* ff_w2  = (const float*)d_in[9];
    const float* ff_b2  = (const float*)d_in[10];
    const float* ln1w   = (const float*)d_in[11];
    const float* ln1b   = (const float*)d_in[12];
    const float* ln2w   = (const float*)d_in[13];
    const float* ln2b   = (const float*)d_in[14];
    float* out = (float*)d_out;

    float* x1;
    __half *h, *q, *k, *v, *a, *f;
    __half *wqh, *wkh, *wvh, *wph, *w1h, *w2h;
    cudaGetSymbolAddress((void**)&x1, g_x1);
    cudaGetSymbolAddress((void**)&h,  g_h);
    cudaGetSymbolAddress((void**)&q,  g_q);
    cudaGetSymbolAddress((void**)&k,  g_k);
    cudaGetSymbolAddress((void**)&v,  g_v);
    cudaGetSymbolAddress((void**)&a,  g_a);
    cudaGetSymbolAddress((void**)&f,  g_f);
    cudaGetSymbolAddress((void**)&wqh, g_wq);
    cudaGetSymbolAddress((void**)&wkh, g_wk);
    cudaGetSymbolAddress((void**)&wvh, g_wv);
    cudaGetSymbolAddress((void**)&wph, g_wp);
    cudaGetSymbolAddress((void**)&w1h, g_w1);
    cudaGetSymbolAddress((void**)&w2h, g_w2);

    cudaFuncSetAttribute((const void*)flashtc_kernel,
                         cudaFuncAttributeMaxDynamicSharedMemorySize, FL_SMEM);
    cudaFuncSetAttribute((const void*)tgemm_kernel<1>,
                         cudaFuncAttributeMaxDynamicSharedMemorySize, GEMM_SMEM);
    cudaFuncSetAttribute((const void*)tgemm_kernel<2>,
                         cudaFuncAttributeMaxDynamicSharedMemorySize, GEMM_SMEM);
    cudaFuncSetAttribute((const void*)tgemm_kernel<3>,
                         cudaFuncAttributeMaxDynamicSharedMemorySize, GEMM_SMEM);
    cudaFuncSetAttribute((const void*)tgemm_kernel<4>,
                         cudaFuncAttributeMaxDynamicSharedMemorySize, GEMM_SMEM);

    // weight transpose -> fp16 (deterministic, every launch)
    wconv_kernel<<<dim3(CEMB / 32, CEMB / 32), 256>>>(wq,     wqh, CEMB, CEMB);
    wconv_kernel<<<dim3(CEMB / 32, CEMB / 32), 256>>>(wk,     wkh, CEMB, CEMB);
    wconv_kernel<<<dim3(CEMB / 32, CEMB / 32), 256>>>(wv,     wvh, CEMB, CEMB);
    wconv_kernel<<<dim3(CEMB / 32, CEMB / 32), 256>>>(proj_w, wph, CEMB, CEMB);
    wconv_kernel<<<dim3(DFF / 32,  CEMB / 32), 256>>>(ff_w1,  w1h, CEMB, DFF);
    wconv_kernel<<<dim3(CEMB / 32, DFF / 32),  256>>>(ff_w2,  w2h, DFF,  CEMB);

    // 1) h = LN1(x) -> fp16
    ln_kernel<<<MTOT, 256>>>(x, ln1w, ln1b, h);

    // 2) q,k,v = h @ W -> fp16 (MODE 4)
    dim3 gC(CEMB / 128, MTOT / 128);
    tgemm_kernel<4><<<gC, 256, GEMM_SMEM>>>(h, wqh, nullptr, q,
                                            nullptr, nullptr, nullptr, MTOT, CEMB, CEMB);
    tgemm_kernel<4><<<gC, 256, GEMM_SMEM>>>(h, wkh, nullptr, k,
                                            nullptr, nullptr, nullptr, MTOT, CEMB, CEMB);
    tgemm_kernel<4><<<gC, 256, GEMM_SMEM>>>(h, wvh, nullptr, v,
                                            nullptr, nullptr, nullptr, MTOT, CEMB, CEMB);

    // 3) causal flash attention (tensor cores) -> fp16
    flashtc_kernel<<<dim3(TSEQ / 64, 4 * 16), 128, FL_SMEM>>>(q, k, v, a);

    // 4) x1 = x + att @ proj_w + proj_b
    tgemm_kernel<1><<<gC, 256, GEMM_SMEM>>>(a, wph, x1, nullptr,
                                            x, proj_b, nullptr, MTOT, CEMB, CEMB);

    // 5) h = LN2(x1) -> fp16
    ln_kernel<<<MTOT, 256>>>(x1, ln2w, ln2b, h);

    // 6) f = fp16(relu(h @ W1 + b1))
    tgemm_kernel<2><<<dim3(DFF / 128, MTOT / 128), 256, GEMM_SMEM>>>(
        h, w1h, nullptr, f, nullptr, ff_b1, nullptr, MTOT, DFF, CEMB);

    // 7) out = (x1 + f @ W2 + b2) * mask(row)
    tgemm_kernel<3><<<gC, 256, GEMM_SMEM>>>(f, w2h, out, nullptr,
                                            x1, ff_b2, mask, MTOT, CEMB, DFF);
}

// round 17
// speedup vs baseline: 13.2158x; 1.6969x over previous
#include <cuda_runtime.h>
#include <cuda_fp16.h>
#include <cstdint>
#include <math.h>

// Problem constants
#define TSEQ 2048
#define CEMB 1024
#define MTOT 8192   // B*T
#define DFF  4096
#define QKVS 3072   // fused qkv row stride

// ---------------- scratch (device globals; no allocation allowed) ------------
__device__ float g_x1[(size_t)MTOT * CEMB];

__device__ __half g_h  [(size_t)MTOT * CEMB];
__device__ __half g_qkv[(size_t)MTOT * QKVS];
__device__ __half g_a  [(size_t)MTOT * CEMB];
__device__ __half g_f  [(size_t)MTOT * DFF];

// transposed weights: B[n][k] = W[k][n], fp16
__device__ __half g_wqkv[(size_t)QKVS * CEMB];   // rows 0..1023 wq^T | wk^T | wv^T
__device__ __half g_wp  [(size_t)CEMB * CEMB];
__device__ __half g_w1  [(size_t)DFF * CEMB];
__device__ __half g_w2  [(size_t)CEMB * DFF];

// ---------------- helpers (baseline ISA only) --------------------------------
__device__ __forceinline__ uint32_t smem_u32(const void* p) {
    uint32_t a;
    asm("{ .reg .u64 t; cvta.to.shared.u64 t, %1; cvt.u32.u64 %0, t; }" : "=r"(a) : "l"(p));
    return a;
}
__device__ __forceinline__ void cp16(uint32_t dst, const void* src) {
    asm volatile("cp.async.cg.shared.global [%0], [%1], 16;" :: "r"(dst), "l"(src));
}
__device__ __forceinline__ void ldsm4(uint32_t* r, uint32_t addr) {
    asm volatile("ldmatrix.sync.aligned.m8n8.x4.shared.b16 {%0,%1,%2,%3}, [%4];"
        : "=r"(r[0]), "=r"(r[1]), "=r"(r[2]), "=r"(r[3]) : "r"(addr));
}
__device__ __forceinline__ void ldsm4t(uint32_t* r, uint32_t addr) {
    asm volatile("ldmatrix.sync.aligned.m8n8.x4.trans.shared.b16 {%0,%1,%2,%3}, [%4];"
        : "=r"(r[0]), "=r"(r[1]), "=r"(r[2]), "=r"(r[3]) : "r"(addr));
}
__device__ __forceinline__ void mma16816(float* c, const uint32_t* a, const uint32_t* b) {
    asm volatile("mma.sync.aligned.m16n8k16.row.col.f32.f16.f16.f32 "
        "{%0,%1,%2,%3}, {%4,%5,%6,%7}, {%8,%9}, {%0,%1,%2,%3};"
        : "+f"(c[0]), "+f"(c[1]), "+f"(c[2]), "+f"(c[3])
        : "r"(a[0]), "r"(a[1]), "r"(a[2]), "r"(a[3]), "r"(b[0]), "r"(b[1]));
}
__device__ __forceinline__ uint32_t pack_h2(float a, float b) {
    __half2 t = __floats2half2_rn(a, b);
    return *reinterpret_cast<uint32_t*>(&t);
}
#define SWZ(x) ((x) ^ (((x) >> 3) & 0x70))

// ---------------- LayerNorm -> fp16 ------------------------------------------
__global__ __launch_bounds__(256)
void ln_kernel(const float* __restrict__ x, const float* __restrict__ w,
               const float* __restrict__ bb, __half* __restrict__ oh)
{
    __shared__ float sred[8];
    __shared__ float s_mu, s_var;
    const int row = blockIdx.x;
    const int tid = threadIdx.x;

    float4 v = ((const float4*)(x + (size_t)row * CEMB))[tid];
    float s = v.x + v.y + v.z + v.w;
    #pragma unroll
    for (int o = 16; o > 0; o >>= 1) s += __shfl_down_sync(0xffffffffu, s, o);
    if ((tid & 31) == 0) sred[tid >> 5] = s;
    __syncthreads();
    if (tid == 0) {
        float t = 0.f;
        #pragma unroll
        for (int i = 0; i < 8; i++) t += sred[i];
        s_mu = t * (1.f / 1024.f);
    }
    __syncthreads();
    const float mu = s_mu;
    float a0 = v.x - mu, a1 = v.y - mu, a2 = v.z - mu, a3 = v.w - mu;
    float sq = a0 * a0 + a1 * a1 + a2 * a2 + a3 * a3;
    #pragma unroll
    for (int o = 16; o > 0; o >>= 1) sq += __shfl_down_sync(0xffffffffu, sq, o);
    if ((tid & 31) == 0) sred[tid >> 5] = sq;
    __syncthreads();
    if (tid == 0) {
        float t = 0.f;
        #pragma unroll
        for (int i = 0; i < 8; i++) t += sred[i];
        s_var = t * (1.f / 1024.f);
    }
    __syncthreads();
    const float r = rsqrtf(s_var + 1e-5f);
    float4 wv = ((const float4*)w)[tid];
    float4 bv = ((const float4*)bb)[tid];
    float o0 = a0 * r * wv.x + bv.x;
    float o1 = a1 * r * wv.y + bv.y;
    float o2 = a2 * r * wv.z + bv.z;
    float o3 = a3 * r * wv.w + bv.w;
    const size_t base = (size_t)row * CEMB + tid * 4;
    ((__half2*)(oh + base))[0] = __floats2half2_rn(o0, o1);
    ((__half2*)(oh + base))[1] = __floats2half2_rn(o2, o3);
}

// ---------------- weight transpose: W[K,N] -> B[N,K] fp16 --------------------
__global__ __launch_bounds__(256)
void wconv_kernel(const float* __restrict__ W, __half* __restrict__ Bh, int K, int N)
{
    __shared__ float t[32][33];
    const int tx = threadIdx.x & 31, ty = threadIdx.x >> 5;
    const int n0 = blockIdx.x * 32, k0 = blockIdx.y * 32;
    #pragma unroll
    for (int r = 0; r < 32; r += 8)
        t[ty + r][tx] = W[(size_t)(k0 + ty + r) * N + n0 + tx];
    __syncthreads();
    #pragma unroll
    for (int r = 0; r < 32; r += 8)
        Bh[(size_t)(n0 + ty + r) * K + k0 + tx] = __float2half_rn(t[tx][ty + r]);
}

// ---------------- tensor-core GEMM (mma.sync fp16): C = A @ B^T --------------
// CTA tile 128(M) x 256(N), 8 warps (2m x 4n), warp tile 64x64. K-tile 64.
// MODE 1: Cf = Rg + acc + bias
// MODE 2: Ch = fp16(relu(acc + bias))
// MODE 3: Cf = (Rg + acc + bias) * mask(row)
// MODE 4: Ch = fp16(acc)
#define STAGE_BYTES 49152                 // A 16K | B 32K
#define NSTAGE      4
#define GEMM_SMEM   (NSTAGE * STAGE_BYTES)

template<int MODE>
__global__ __launch_bounds__(256, 1)
void tgemm_kernel(const __half* __restrict__ Ah, const __half* __restrict__ Bh,
                  float* __restrict__ Cf, __half* __restrict__ Ch,
                  const float* __restrict__ Rg, const float* __restrict__ biasg,
                  const unsigned char* __restrict__ maskg, int M, int N, int K)
{
    extern __shared__ char smem[];
    const uint32_t sb = smem_u32(smem);
    const int tid    = threadIdx.x;
    const int lane   = tid & 31;
    const int wid    = tid >> 5;
    const int warp_m = wid & 1;    // 2 x 64 rows
    const int warp_n = wid >> 1;   // 4 x 64 cols
    const int brow   = blockIdx.y * 128;
    const int bcol   = blockIdx.x * 256;

    const __half* gA = Ah + (size_t)brow * K;
    const __half* gB = Bh + (size_t)bcol * K;

    float acc[4][8][4];
    #pragma unroll
    for (int m = 0; m < 4; m++)
        #pragma unroll
        for (int nt = 0; nt < 8; nt++)
            #pragma unroll
            for (int e = 0; e < 4; e++) acc[m][nt][e] = 0.f;

    const int a_row_l = (lane & 15);
    const int a_kh    = lane >> 4;
    const int b_row_l = ((lane >> 4) & 1) * 8 + (lane & 7);
    const int b_kh    = (lane >> 3) & 1;

    const int NKT = K >> 6;

    // Per stage: A 128 rows x 128B (1024 chunks) + B 256 rows x 128B (2048 chunks)
#define LOAD_STAGE(KT) do {                                                        \
        if ((KT) < NKT) {                                                          \
            const uint32_t st_ = sb + ((KT) % NSTAGE) * STAGE_BYTES;               \
            const int k0_ = (KT) * 64;                                             \
            _Pragma("unroll")                                                      \
            for (int c = 0; c < 4; c++) {                                          \
                const int lin = tid + c * 256;         /* 0..1023 */               \
                const int row = lin >> 3, ch = lin & 7;                            \
                cp16(st_ + SWZ(row * 128 + ch * 16),                               \
                     gA + (size_t)row * K + k0_ + ch * 8);                         \
            }                                                                      \
            _Pragma("unroll")                                                      \
            for (int c = 0; c < 8; c++) {                                          \
                const int lin = tid + c * 256;         /* 0..2047 */               \
                const int row = lin >> 3, ch = lin & 7;                            \
                cp16(st_ + 16384 + SWZ(row * 128 + ch * 16),                       \
                     gB + (size_t)row * K + k0_ + ch * 8);                         \
            }                                                                      \
        }                                                                          \
        asm volatile("cp.async.commit_group;" ::: "memory");                       \
    } while (0)

    LOAD_STAGE(0);
    LOAD_STAGE(1);
    LOAD_STAGE(2);

    for (int kt = 0; kt < NKT; kt++) {
        asm volatile("cp.async.wait_group 2;" ::: "memory");
        __syncthreads();
        LOAD_STAGE(kt + 3);

        const uint32_t st = sb + (kt % NSTAGE) * STAGE_BYTES;
        #pragma unroll
        for (int kk = 0; kk < 4; kk++) {
            uint32_t ah[4][4];
            #pragma unroll
            for (int m = 0; m < 4; m++) {
                const uint32_t off = SWZ((warp_m * 64 + m * 16 + a_row_l) * 128
                                         + (2 * kk + a_kh) * 16);
                ldsm4(ah[m], st + off);
            }
            uint32_t bh[4][4];
            #pragma unroll
            for (int nt2 = 0; nt2 < 4; nt2++) {
                const uint32_t off = SWZ((warp_n * 64 + nt2 * 16 + b_row_l) * 128
                                         + (2 * kk + b_kh) * 16);
                ldsm4(bh[nt2], st + 16384 + off);
            }
            #pragma unroll
            for (int m = 0; m < 4; m++)
                #pragma unroll
                for (int nt2 = 0; nt2 < 4; nt2++)
                    #pragma unroll
                    for (int half = 0; half < 2; half++)
                        mma16816(acc[m][nt2 * 2 + half], ah[m], &bh[nt2][half * 2]);
        }
        __syncthreads();
    }
#undef LOAD_STAGE

    // ---------------- epilogue ----------------
    unsigned int probe = 0;
    if (MODE == 3) probe = (unsigned int)maskg[1];  // t=1 always valid (len>=1024)

    const int rbase = brow + warp_m * 64 + (lane >> 2);
    const int cbase = bcol + warp_n * 64 + (lane & 3) * 2;

    #pragma unroll
    for (int m = 0; m < 4; m++) {
        const size_t rowA = (size_t)(rbase + m * 16);
        const size_t rowB = rowA + 8;
        float mA = 1.f, mB = 1.f;
        if (MODE == 3) {
            mA = probe ? (maskg[rowA] ? 1.f : 0.f)
                       : (((const unsigned int*)maskg)[rowA] ? 1.f : 0.f);
            mB = probe ? (maskg[rowB] ? 1.f : 0.f)
                       : (((const unsigned int*)maskg)[rowB] ? 1.f : 0.f);
        }
        #pragma unroll
        for (int nt = 0; nt < 8; nt++) {
            const int col = cbase + nt * 8;
            float o0 = acc[m][nt][0], o1 = acc[m][nt][1];   // rowA
            float o2 = acc[m][nt][2], o3 = acc[m][nt][3];   // rowB
            if (MODE == 1 || MODE == 3) {
                float2 rA = *(const float2*)(Rg + rowA * N + col);
                float2 rB = *(const float2*)(Rg + rowB * N + col);
                o0 += rA.x; o1 += rA.y; o2 += rB.x; o3 += rB.y;
            }
            if (MODE == 1 || MODE == 2 || MODE == 3) {
                float2 bv = *(const float2*)(biasg + col);
                o0 += bv.x; o1 += bv.y; o2 += bv.x; o3 += bv.y;
            }
            if (MODE == 2) {
                o0 = fmaxf(o0, 0.f); o1 = fmaxf(o1, 0.f);
                o2 = fmaxf(o2, 0.f); o3 = fmaxf(o3, 0.f);
            }
            if (MODE == 2 || MODE == 4) {
                *(__half2*)(Ch + rowA * N + col) = __floats2half2_rn(o0, o1);
                *(__half2*)(Ch + rowB * N + col) = __floats2half2_rn(o2, o3);
            } else {
                if (MODE == 3) { o0 *= mA; o1 *= mA; o2 *= mB; o3 *= mB; }
                *(float2*)(Cf + rowA * N + col) = make_float2(o0, o1);
                *(float2*)(Cf + rowB * N + col) = make_float2(o2, o3);
            }
        }
    }
}

// ---------------- Flash attention (causal), tensor-core fp16 -----------------
// grid (T/64, B*H); 128 threads = 4 warps, 16 q-rows per warp, KV tile 64.
// Reads fused qkv buffer (row stride QKVS; q/k/v at offsets 0/1024/2048).
// smem: Q 8KB | stage0 16KB (K,V) | stage1 16KB
#define FL_SMEM (8192 + 2 * 16384)

__global__ __launch_bounds__(128)
void flashtc_kernel(const __half* __restrict__ qkv, __half* __restrict__ oh_)
{
    extern __shared__ char smch[];
    const uint32_t sb = smem_u32(smch);
    const int qt  = blockIdx.x;
    const int bh  = blockIdx.y;
    const int bb  = bh >> 4;
    const int h   = bh & 15;
    const int tid = threadIdx.x;
    const int lane = tid & 31;
    const int w    = tid >> 5;
    const size_t rowbase = (size_t)bb * TSEQ;
    const int hoff = h * 64;

    const int a_row = lane & 15, a_kh = lane >> 4;
    const int b_row = ((lane >> 4) & 1) * 8 + (lane & 7);
    const int b_kh  = (lane >> 3) & 1;
    const int v_row = ((lane >> 3) & 1) * 8 + (lane & 7);
    const int v_db  = (lane >> 4) * 16;

#define LOAD_64x64(qkvoff, trow, dst) do {                                         \
        _Pragma("unroll")                                                          \
        for (int c = 0; c < 4; c++) {                                              \
            const int idx = tid + c * 128;                                         \
            const int r_ = idx >> 3, ch_ = idx & 7;                                \
            cp16((dst) + SWZ(r_ * 128 + ch_ * 16),                                 \
                 qkv + (rowbase + (trow) + r_) * QKVS + (qkvoff) + hoff + ch_ * 8);\
        }                                                                          \
    } while (0)
#define LOAD_KV(JT) do {                                                           \
        const uint32_t stb_ = sb + 8192 + ((JT) & 1) * 16384;                      \
        LOAD_64x64(1024, (JT) * 64, stb_);                                         \
        LOAD_64x64(2048, (JT) * 64, stb_ + 8192);                                  \
        asm volatile("cp.async.commit_group;" ::: "memory");                       \
    } while (0)

    // Q tile (own group) + KV stage 0
    LOAD_64x64(0, qt * 64, sb);
    asm volatile("cp.async.commit_group;" ::: "memory");
    LOAD_KV(0);
    asm volatile("cp.async.wait_group 1;" ::: "memory");   // Q ready
    __syncthreads();

    uint32_t qf[4][4];
    #pragma unroll
    for (int kk = 0; kk < 4; kk++) {
        const uint32_t off = SWZ((w * 16 + a_row) * 128 + (2 * kk + a_kh) * 16);
        ldsm4(qf[kk], sb + off);
    }

    float oacc[8][4];
    #pragma unroll
    for (int nt = 0; nt < 8; nt++)
        #pragma unroll
        for (int e = 0; e < 4; e++) oacc[nt][e] = 0.f;
    float m0 = -1e30f, m1 = -1e30f, l0 = 0.f, l1 = 0.f;

    const int row0 = qt * 64 + w * 16 + (lane >> 2);
    const int row1 = row0 + 8;
    const float scale = 0.03125f;  // 1024^-0.5

    for (int jt = 0; jt <= qt; jt++) {
        if (jt + 1 <= qt) {
            LOAD_KV(jt + 1);
            asm volatile("cp.async.wait_group 1;" ::: "memory");
        } else {
            asm volatile("cp.async.wait_group 0;" ::: "memory");
        }
        __syncthreads();

        const uint32_t st = sb + 8192 + (jt & 1) * 16384;

        // ---- S = Q K^T
        float sacc[8][4];
        #pragma unroll
        for (int nt = 0; nt < 8; nt++)
            #pragma unroll
            for (int e = 0; e < 4; e++) sacc[nt][e] = 0.f;
        #pragma unroll
        for (int kk = 0; kk < 4; kk++) {
            #pragma unroll
            for (int nt2 = 0; nt2 < 4; nt2++) {
                uint32_t kf[4];
                const uint32_t off = SWZ((nt2 * 16 + b_row) * 128 + (2 * kk + b_kh) * 16);
                ldsm4(kf, st + off);
                mma16816(sacc[nt2 * 2],     qf[kk], &kf[0]);
                mma16816(sacc[nt2 * 2 + 1], qf[kk], &kf[2]);
            }
        }

        // ---- scale + causal mask + tile row max
        float tm0 = -1e30f, tm1 = -1e30f;
        #pragma unroll
        for (int nt = 0; nt < 8; nt++) {
            const int col = jt * 64 + nt * 8 + (lane & 3) * 2;
            float s0 = sacc[nt][0] * scale;
            float s1 = sacc[nt][1] * scale;
            float s2 = sacc[nt][2] * scale;
            float s3 = sacc[nt][3] * scale;
            if (jt == qt) {
                if (col     > row0) s0 = -1e30f;
                if (col + 1 > row0) s1 = -1e30f;
                if (col     > row1) s2 = -1e30f;
                if (col + 1 > row1) s3 = -1e30f;
            }
            sacc[nt][0] = s0; sacc[nt][1] = s1; sacc[nt][2] = s2; sacc[nt][3] = s3;
            tm0 = fmaxf(tm0, fmaxf(s0, s1));
            tm1 = fmaxf(tm1, fmaxf(s2, s3));
        }
        tm0 = fmaxf(tm0, __shfl_xor_sync(0xffffffffu, tm0, 1));
        tm0 = fmaxf(tm0, __shfl_xor_sync(0xffffffffu, tm0, 2));
        tm1 = fmaxf(tm1, __shfl_xor_sync(0xffffffffu, tm1, 1));
        tm1 = fmaxf(tm1, __shfl_xor_sync(0xffffffffu, tm1, 2));

        const float mn0 = fmaxf(m0, tm0), mn1 = fmaxf(m1, tm1);
        const float al0 = __expf(m0 - mn0), al1 = __expf(m1 - mn1);
        m0 = mn0; m1 = mn1;

        // ---- P = exp(S - m), row sums
        float rs0 = 0.f, rs1 = 0.f;
        #pragma unroll
        for (int nt = 0; nt < 8; nt++) {
            float p0 = __expf(sacc[nt][0] - mn0);
            float p1 = __expf(sacc[nt][1] - mn0);
            float p2 = __expf(sacc[nt][2] - mn1);
            float p3 = __expf(sacc[nt][3] - mn1);
            sacc[nt][0] = p0; sacc[nt][1] = p1; sacc[nt][2] = p2; sacc[nt][3] = p3;
            rs0 += p0 + p1; rs1 += p2 + p3;
        }
        rs0 += __shfl_xor_sync(0xffffffffu, rs0, 1);
        rs0 += __shfl_xor_sync(0xffffffffu, rs0, 2);
        rs1 += __shfl_xor_sync(0xffffffffu, rs1, 1);
        rs1 += __shfl_xor_sync(0xffffffffu, rs1, 2);
        l0 = l0 * al0 + rs0;
        l1 = l1 * al1 + rs1;

        // ---- rescale O
        #pragma unroll
        for (int nt = 0; nt < 8; nt++) {
            oacc[nt][0] *= al0; oacc[nt][1] *= al0;
            oacc[nt][2] *= al1; oacc[nt][3] *= al1;
        }

        // ---- O += P V ; P fragments re-packed from S accumulators
        #pragma unroll
        for (int kk2 = 0; kk2 < 4; kk2++) {
            const int t0 = kk2 * 2, t1 = t0 + 1;
            uint32_t pa[4];
            pa[0] = pack_h2(sacc[t0][0], sacc[t0][1]);
            pa[1] = pack_h2(sacc[t0][2], sacc[t0][3]);
            pa[2] = pack_h2(sacc[t1][0], sacc[t1][1]);
            pa[3] = pack_h2(sacc[t1][2], sacc[t1][3]);
            #pragma unroll
            for (int nt2 = 0; nt2 < 4; nt2++) {
                uint32_t v4[4];
                const uint32_t voff = SWZ((kk2 * 16 + v_row) * 128 + nt2 * 32 + v_db);
                ldsm4t(v4, st + 8192 + voff);
                mma16816(oacc[nt2 * 2],     pa, &v4[0]);
                mma16816(oacc[nt2 * 2 + 1], pa, &v4[2]);
            }
        }
        __syncthreads();   // all warps done with this stage before reload
    }
#undef LOAD_KV
#undef LOAD_64x64

    // ---- epilogue: O / l -> fp16
    const float inv0 = 1.f / l0, inv1 = 1.f / l1;
    const size_t gr0 = (rowbase + (size_t)row0) * CEMB + hoff;
    const size_t gr1 = (rowbase + (size_t)row1) * CEMB + hoff;
    #pragma unroll
    for (int nt = 0; nt < 8; nt++) {
        const int col = nt * 8 + (lane & 3) * 2;
        *(__half2*)(oh_ + gr0 + col) = __floats2half2_rn(oacc[nt][0] * inv0, oacc[nt][1] * inv0);
        *(__half2*)(oh_ + gr1 + col) = __floats2half2_rn(oacc[nt][2] * inv1, oacc[nt][3] * inv1);
    }
}

// ---------------- launcher ---------------------------------------------------
extern "C" void kernel_launch(void* const* d_in, const int* in_sizes, int n_in,
                              void* d_out, int out_size)
{
    const float* x      = (const float*)d_in[0];
    const unsigned char* mask = (const unsigned char*)d_in[1];
    const float* wq     = (const float*)d_in[2];
    const float* wk     = (const float*)d_in[3];
    const float* wv     = (const float*)d_in[4];
    const float* proj_w = (const float*)d_in[5];
    const float* proj_b = (const float*)d_in[6];
    const float* ff_w1  = (const float*)d_in[7];
    const float* ff_b1  = (const float*)d_in[8];
    const float* ff_w2  = (const float*)d_in[9];
    const float* ff_b2  = (const float*)d_in[10];
    const float* ln1w   = (const float*)d_in[11];
    const float* ln1b   = (const float*)d_in[12];
    const float* ln2w   = (const float*)d_in[13];
    const float* ln2b   = (const float*)d_in[14];
    float* out = (float*)d_out;

    float* x1;
    __half *h, *qkv, *a, *f;
    __half *wqkv, *wph, *w1h, *w2h;
    cudaGetSymbolAddress((void**)&x1,  g_x1);
    cudaGetSymbolAddress((void**)&h,   g_h);
    cudaGetSymbolAddress((void**)&qkv, g_qkv);
    cudaGetSymbolAddress((void**)&a,   g_a);
    cudaGetSymbolAddress((void**)&f,   g_f);
    cudaGetSymbolAddress((void**)&wqkv, g_wqkv);
    cudaGetSymbolAddress((void**)&wph,  g_wp);
    cudaGetSymbolAddress((void**)&w1h,  g_w1);
    cudaGetSymbolAddress((void**)&w2h,  g_w2);

    cudaFuncSetAttribute((const void*)flashtc_kernel,
                         cudaFuncAttributeMaxDynamicSharedMemorySize, FL_SMEM);
    cudaFuncSetAttribute((const void*)tgemm_kernel<1>,
                         cudaFuncAttributeMaxDynamicSharedMemorySize, GEMM_SMEM);
    cudaFuncSetAttribute((const void*)tgemm_kernel<2>,
                         cudaFuncAttributeMaxDynamicSharedMemorySize, GEMM_SMEM);
    cudaFuncSetAttribute((const void*)tgemm_kernel<3>,
                         cudaFuncAttributeMaxDynamicSharedMemorySize, GEMM_SMEM);
    cudaFuncSetAttribute((const void*)tgemm_kernel<4>,
                         cudaFuncAttributeMaxDynamicSharedMemorySize, GEMM_SMEM);

    // weight transpose -> fp16 (deterministic, every launch)
    // fused qkv weight: rows 0..1023 wq^T | 1024..2047 wk^T | 2048..3071 wv^T
    wconv_kernel<<<dim3(CEMB / 32, CEMB / 32), 256>>>(wq,     wqkv,                    CEMB, CEMB);
    wconv_kernel<<<dim3(CEMB / 32, CEMB / 32), 256>>>(wk,     wqkv + (size_t)CEMB * CEMB,     CEMB, CEMB);
    wconv_kernel<<<dim3(CEMB / 32, CEMB / 32), 256>>>(wv,     wqkv + (size_t)2 * CEMB * CEMB, CEMB, CEMB);
    wconv_kernel<<<dim3(CEMB / 32, CEMB / 32), 256>>>(proj_w, wph, CEMB, CEMB);
    wconv_kernel<<<dim3(DFF / 32,  CEMB / 32), 256>>>(ff_w1,  w1h, CEMB, DFF);
    wconv_kernel<<<dim3(CEMB / 32, DFF / 32),  256>>>(ff_w2,  w2h, DFF,  CEMB);

    // 1) h = LN1(x) -> fp16
    ln_kernel<<<MTOT, 256>>>(x, ln1w, ln1b, h);

    // 2) qkv = h @ Wqkv -> fp16 (fused, MODE 4), N=3072
    tgemm_kernel<4><<<dim3(QKVS / 256, MTOT / 128), 256, GEMM_SMEM>>>(
        h, wqkv, nullptr, qkv, nullptr, nullptr, nullptr, MTOT, QKVS, CEMB);

    // 3) causal flash attention (tensor cores) -> fp16
    flashtc_kernel<<<dim3(TSEQ / 64, 4 * 16), 128, FL_SMEM>>>(qkv, a);

    // 4) x1 = x + att @ proj_w + proj_b
    tgemm_kernel<1><<<dim3(CEMB / 256, MTOT / 128), 256, GEMM_SMEM>>>(
        a, wph, x1, nullptr, x, proj_b, nullptr, MTOT, CEMB, CEMB);

    // 5) h = LN2(x1) -> fp16
    ln_kernel<<<MTOT, 256>>>(x1, ln2w, ln2b, h);

    // 6) f = fp16(relu(h @ W1 + b1))
    tgemm_kernel<2><<<dim3(DFF / 256, MTOT / 128), 256, GEMM_SMEM>>>(
        h, w1h, nullptr, f, nullptr, ff_b1, nullptr, MTOT, DFF, CEMB);

    // 7) out = (x1 + f @ W2 + b2) * mask(row)
    tgemm_kernel<3><<<dim3(CEMB / 256, MTOT / 128), 256, GEMM_SMEM>>>(
        f, w2h, out, nullptr, x1, ff_b2, mask, MTOT, CEMB, DFF);
}